// round 9
// baseline (speedup 1.0000x reference)
#include <cuda_runtime.h>
#include <cuda_bf16.h>
#include <cstdint>
#include <math.h>

// ---------------------------------------------------------------------------
// Problem constants
// ---------------------------------------------------------------------------
#define B_SZ    2
#define S_LEN   2048
#define D_MODEL 1024
#define NHEAD   16
#define DKH     64
#define MROWS   4096
#define KDIM    1024
#define NDIM    1024
#define NQT     (S_LEN / 128)     // 16 q-tiles

// ---------------------------------------------------------------------------
// Scratch (device globals)
// ---------------------------------------------------------------------------
__device__ __align__(16) __nv_bfloat16 g_xh [MROWS * KDIM];
__device__ __align__(16) __nv_bfloat16 g_xl [MROWS * KDIM];
__device__ __align__(16) __nv_bfloat16 g_wh [4 * KDIM * NDIM];
__device__ __align__(16) __nv_bfloat16 g_wl [4 * KDIM * NDIM];
__device__ __align__(16) __nv_bfloat16 g_qh [MROWS * D_MODEL];
__device__ __align__(16) __nv_bfloat16 g_ql [MROWS * D_MODEL];
__device__ __align__(16) __nv_bfloat16 g_kh [MROWS * D_MODEL];
__device__ __align__(16) __nv_bfloat16 g_kl [MROWS * D_MODEL];
__device__ __align__(16) __nv_bfloat16 g_vh [MROWS * D_MODEL];
__device__ __align__(16) __nv_bfloat16 g_vl [MROWS * D_MODEL];
__device__ __align__(16) __nv_bfloat16 g_aoh[MROWS * D_MODEL];
__device__ __align__(16) __nv_bfloat16 g_aol[MROWS * D_MODEL];

// ---------------------------------------------------------------------------
// PTX helpers (sm_80-era, valid at compute_100)
// ---------------------------------------------------------------------------
__device__ __forceinline__ uint32_t smem_u32(const void* p) {
    uint32_t a;
    asm("{ .reg .u64 t; cvta.to.shared.u64 t, %1; cvt.u32.u64 %0, t; }"
        : "=r"(a) : "l"(p));
    return a;
}

__device__ __forceinline__ void cp_async16(uint32_t dst, const void* src) {
    asm volatile("cp.async.cg.shared.global [%0], [%1], 16;"
                 :: "r"(dst), "l"(src) : "memory");
}
#define CP_COMMIT() asm volatile("cp.async.commit_group;" ::: "memory")
#define CP_WAIT(n)  asm volatile("cp.async.wait_group %0;" :: "n"(n) : "memory")

#define LDSM4(r, addr) \
    asm volatile("ldmatrix.sync.aligned.m8n8.x4.shared.b16 {%0,%1,%2,%3}, [%4];" \
                 : "=r"((r)[0]), "=r"((r)[1]), "=r"((r)[2]), "=r"((r)[3]) : "r"(addr))

#define LDSM4T(r, addr) \
    asm volatile("ldmatrix.sync.aligned.m8n8.x4.trans.shared.b16 {%0,%1,%2,%3}, [%4];" \
                 : "=r"((r)[0]), "=r"((r)[1]), "=r"((r)[2]), "=r"((r)[3]) : "r"(addr))

#define MMA16816(d, a, b0v, b1v) \
    asm volatile("mma.sync.aligned.m16n8k16.row.col.f32.bf16.bf16.f32 " \
                 "{%0,%1,%2,%3}, {%4,%5,%6,%7}, {%8,%9}, {%0,%1,%2,%3};" \
                 : "+f"((d)[0]), "+f"((d)[1]), "+f"((d)[2]), "+f"((d)[3]) \
                 : "r"((a)[0]), "r"((a)[1]), "r"((a)[2]), "r"((a)[3]), \
                   "r"(b0v), "r"(b1v))

__device__ __forceinline__ uint32_t bf2x(float hi, float lo) {
    uint32_t d;
    asm("cvt.rn.bf16x2.f32 %0, %1, %2;" : "=r"(d) : "f"(hi), "f"(lo));
    return d;
}
__device__ __forceinline__ float bf_round(float x) {
    return __bfloat162float(__float2bfloat16_rn(x));
}

// ---------------------------------------------------------------------------
// fp32 -> bf16 hi/lo splits (x; and all 4 weights in one launch)
// ---------------------------------------------------------------------------
__global__ __launch_bounds__(256)
void split_bf16(const float* __restrict__ in, __nv_bfloat16* __restrict__ hi,
                __nv_bfloat16* __restrict__ lo, int n4)
{
    int i = blockIdx.x * blockDim.x + threadIdx.x;
    if (i >= n4) return;
    float4 v = ((const float4*)in)[i];
    float f[4] = {v.x, v.y, v.z, v.w};
    unsigned short hs[4], ls[4];
    #pragma unroll
    for (int j = 0; j < 4; j++) {
        __nv_bfloat16 h = __float2bfloat16_rn(f[j]);
        float r = f[j] - __bfloat162float(h);
        __nv_bfloat16 l = __float2bfloat16_rn(r);
        hs[j] = __bfloat16_as_ushort(h);
        ls[j] = __bfloat16_as_ushort(l);
    }
    ((ushort4*)hi)[i] = make_ushort4(hs[0], hs[1], hs[2], hs[3]);
    ((ushort4*)lo)[i] = make_ushort4(ls[0], ls[1], ls[2], ls[3]);
}

__global__ __launch_bounds__(256)
void split_w4(const float* __restrict__ w0, const float* __restrict__ w1,
              const float* __restrict__ w2, const float* __restrict__ w3,
              __nv_bfloat16* __restrict__ hi, __nv_bfloat16* __restrict__ lo,
              int n4w)
{
    int i = blockIdx.x * blockDim.x + threadIdx.x;
    if (i >= 4 * n4w) return;
    const int m = i / n4w;
    const int j = i - m * n4w;
    const float* src = (m == 0) ? w0 : (m == 1) ? w1 : (m == 2) ? w2 : w3;
    float4 v = ((const float4*)src)[j];
    float f[4] = {v.x, v.y, v.z, v.w};
    unsigned short hs[4], ls[4];
    #pragma unroll
    for (int jj = 0; jj < 4; jj++) {
        __nv_bfloat16 h = __float2bfloat16_rn(f[jj]);
        float r = f[jj] - __bfloat162float(h);
        __nv_bfloat16 l = __float2bfloat16_rn(r);
        hs[jj] = __bfloat16_as_ushort(h);
        ls[jj] = __bfloat16_as_ushort(l);
    }
    ((ushort4*)hi)[i] = make_ushort4(hs[0], hs[1], hs[2], hs[3]);
    ((ushort4*)lo)[i] = make_ushort4(ls[0], ls[1], ls[2], ls[3]);
}

// ---------------------------------------------------------------------------
// bf16x3-split GEMM via mma.sync:  C = A B^T (NT), 128x256x32 CTA tile.
// 256 threads, 8 warps (2m x 4n), warp tile 64x64. 3-stage cp.async pipeline.
// fused=1: QKV mode — grid (12, M/128); blockIdx.x>>2 selects Wq/Wk/Wv and
//          the (q|k|v) hi/lo outputs (Q scaled 1/8). fused=0: single GEMM,
//          grid (4, M/128), fp32 output Cf.
// ---------------------------------------------------------------------------
#define ATB     10240                 // 128 * 80
#define BTB     20480                 // 256 * 80
#define STG2    (2 * ATB + 2 * BTB)   // 61440
#define GSMEM3  (3 * STG2)            // 184320
#define KT      (KDIM / 32)           // 32

__global__ __launch_bounds__(256, 1)
void gemm_bf16x3(const __nv_bfloat16* __restrict__ Agh,
                 const __nv_bfloat16* __restrict__ Agl,
                 const __nv_bfloat16* __restrict__ Wh,
                 const __nv_bfloat16* __restrict__ Wl,
                 float* __restrict__ Cfin,
                 __nv_bfloat16* __restrict__ C0h, __nv_bfloat16* __restrict__ C0l,
                 __nv_bfloat16* __restrict__ C1h, __nv_bfloat16* __restrict__ C1l,
                 __nv_bfloat16* __restrict__ C2h, __nv_bfloat16* __restrict__ C2l,
                 int fused)
{
    extern __shared__ __align__(128) char smem_raw[];
    const uint32_t smem = smem_u32(smem_raw);

    const int tid    = threadIdx.x;
    const int lane   = tid & 31;
    const int wid    = tid >> 5;
    const int warp_m = wid & 1;
    const int warp_n = wid >> 1;
    const int row0   = blockIdx.y * 128;

    const __nv_bfloat16 *Bgh, *Bgl;
    __nv_bfloat16 *Ch, *Cl2;
    float* Cf;
    float scale;
    int col0;
    if (fused) {
        const int m = blockIdx.x >> 2;
        Bgh  = Wh + (size_t)m * KDIM * NDIM;
        Bgl  = Wl + (size_t)m * KDIM * NDIM;
        col0 = (blockIdx.x & 3) * 256;
        Ch   = (m == 0) ? C0h : (m == 1) ? C1h : C2h;
        Cl2  = (m == 0) ? C0l : (m == 1) ? C1l : C2l;
        scale = (m == 0) ? 0.125f : 1.f;
        Cf = nullptr;
    } else {
        Bgh = Wh; Bgl = Wl;
        col0 = blockIdx.x * 256;
        Ch = nullptr; Cl2 = nullptr;
        scale = 1.f;
        Cf = Cfin;
    }

    const uint32_t aoff = (uint32_t)((lane & 15) * 80 + ((lane >> 4) << 4));
    const uint32_t boff = (uint32_t)((((lane >> 3) & 1) * 8 + (lane & 7)) * 80 +
                                     ((lane >> 4) << 4));

    float acc[4][8][4];
    #pragma unroll
    for (int mt = 0; mt < 4; mt++)
        #pragma unroll
        for (int nt = 0; nt < 8; nt++)
            #pragma unroll
            for (int q = 0; q < 4; q++) acc[mt][nt][q] = 0.f;

    const int r_lo = tid >> 2;
    const int k16  = tid & 3;

    #define LOAD_STAGE(sb, k0)                                                  \
    do {                                                                        \
        const size_t kofs = (size_t)(k0) + k16 * 8;                             \
        _Pragma("unroll")                                                       \
        for (int rr = 0; rr < 2; rr++) {                                        \
            const int r = r_lo + rr * 64;                                       \
            cp_async16((sb) + r * 80 + k16 * 16,                                \
                       Agh + (size_t)(row0 + r) * KDIM + kofs);                 \
            cp_async16((sb) + ATB + r * 80 + k16 * 16,                          \
                       Agl + (size_t)(row0 + r) * KDIM + kofs);                 \
        }                                                                       \
        _Pragma("unroll")                                                       \
        for (int rr = 0; rr < 4; rr++) {                                        \
            const int r = r_lo + rr * 64;                                       \
            cp_async16((sb) + 2 * ATB + r * 80 + k16 * 16,                      \
                       Bgh + (size_t)(col0 + r) * KDIM + kofs);                 \
            cp_async16((sb) + 2 * ATB + BTB + r * 80 + k16 * 16,                \
                       Bgl + (size_t)(col0 + r) * KDIM + kofs);                 \
        }                                                                       \
    } while (0)

    LOAD_STAGE(smem, 0);
    CP_COMMIT();
    LOAD_STAGE(smem + STG2, 32);
    CP_COMMIT();

    int sc = 0;   // compute stage
    int sl = 2;   // load stage (t+2)
    for (int t = 0; t < KT; t++) {
        if (t < KT - 1) { CP_WAIT(1); } else { CP_WAIT(0); }
        __syncthreads();
        if (t + 2 < KT) {
            LOAD_STAGE(smem + sl * STG2, (t + 2) * 32);
            CP_COMMIT();
        }

        const uint32_t sb  = smem + sc * STG2;
        const uint32_t Ahs = sb;
        const uint32_t Bhs = sb + 2 * ATB;

        #pragma unroll
        for (int kk = 0; kk < 2; kk++) {
            const uint32_t kkb = kk * 32;
            uint32_t ah[4][4];
            uint32_t al[4][4];
            uint32_t bh[4][4];
            uint32_t bl[4][4];
            #pragma unroll
            for (int mt = 0; mt < 4; mt++) {
                const uint32_t ad = Ahs + (warp_m * 64 + mt * 16) * 80 + kkb + aoff;
                LDSM4(ah[mt], ad);
                LDSM4(al[mt], ad + ATB);
            }
            #pragma unroll
            for (int p = 0; p < 4; p++) {
                const uint32_t bd = Bhs + (warp_n * 64 + p * 16) * 80 + kkb + boff;
                LDSM4(bh[p], bd);
                LDSM4(bl[p], bd + BTB);
            }
            #pragma unroll
            for (int mt = 0; mt < 4; mt++)
                #pragma unroll
                for (int nt = 0; nt < 8; nt++) {
                    float* d = acc[mt][nt];
                    const int p = nt >> 1;
                    const int q = nt & 1;
                    MMA16816(d, ah[mt], bh[p][q], bh[p][q + 2]);
                    MMA16816(d, ah[mt], bl[p][q], bl[p][q + 2]);
                    MMA16816(d, al[mt], bh[p][q], bh[p][q + 2]);
                }
        }
        sc = (sc == 2) ? 0 : sc + 1;
        sl = (sl == 2) ? 0 : sl + 1;
    }
    #undef LOAD_STAGE

    // ---- epilogue ----
    const int rbase = row0 + warp_m * 64 + (lane >> 2);
    const int cbase = col0 + warp_n * 64 + (lane & 3) * 2;
    #pragma unroll
    for (int mt = 0; mt < 4; mt++) {
        #pragma unroll
        for (int nt = 0; nt < 8; nt++) {
            const int r = rbase + mt * 16;
            const int c = cbase + nt * 8;
            const float v0 = acc[mt][nt][0] * scale;
            const float v1 = acc[mt][nt][1] * scale;
            const float v2 = acc[mt][nt][2] * scale;
            const float v3 = acc[mt][nt][3] * scale;
            if (Cf) {
                *(float2*)&Cf[(size_t)r * NDIM + c]       = make_float2(v0, v1);
                *(float2*)&Cf[(size_t)(r + 8) * NDIM + c] = make_float2(v2, v3);
            }
            if (Ch) {
                const float h0 = bf_round(v0), h1 = bf_round(v1);
                const float h2 = bf_round(v2), h3 = bf_round(v3);
                *(uint32_t*)&Ch[(size_t)r * NDIM + c]        = bf2x(v1, v0);
                *(uint32_t*)&Cl2[(size_t)r * NDIM + c]       = bf2x(v1 - h1, v0 - h0);
                *(uint32_t*)&Ch[(size_t)(r + 8) * NDIM + c]  = bf2x(v3, v2);
                *(uint32_t*)&Cl2[(size_t)(r + 8) * NDIM + c] = bf2x(v3 - h3, v2 - h2);
            }
        }
    }
}

// ---------------------------------------------------------------------------
// Tensor-core causal flash attention, bf16x3 split.
// Chunk c lives in smem stage (c+1)&1 so chunk 0 prefetches during Q load.
// Warp-uniform skip of fully-masked sub-tiles in diagonal chunks.
// ---------------------------------------------------------------------------
#define APITCH  144
#define KV_TILE (64 * APITCH)
#define ASTAGE  (4 * KV_TILE)
#define ASMEM   (2 * ASTAGE)

__global__ __launch_bounds__(256, 1)
void attn_mma(const __nv_bfloat16* __restrict__ Qh_, const __nv_bfloat16* __restrict__ Ql_,
              const __nv_bfloat16* __restrict__ Kh_, const __nv_bfloat16* __restrict__ Kl_,
              const __nv_bfloat16* __restrict__ Vh_, const __nv_bfloat16* __restrict__ Vl_,
              __nv_bfloat16* __restrict__ AOh, __nv_bfloat16* __restrict__ AOl)
{
    extern __shared__ __align__(128) char smx[];
    const uint32_t smem = smem_u32(smx);
    const int tid  = threadIdx.x;
    const int lane = tid & 31;
    const int w    = tid >> 5;
    const int qt   = (NQT - 1) - blockIdx.x;
    const int h    = blockIdx.y;
    const int b    = blockIdx.z;
    const int q0   = qt * 128;
    const int hbase = h * 64;

    const uint32_t aoff = (uint32_t)((lane & 15) * APITCH + ((lane >> 4) << 4));
    const uint32_t boff = (uint32_t)((((lane >> 3) & 1) * 8 + (lane & 7)) * APITCH +
                                     ((lane >> 4) << 4));
    const uint32_t voff = aoff;

    const __nv_bfloat16* kvsrc[4];
    kvsrc[0] = Kh_; kvsrc[1] = Kl_; kvsrc[2] = Vh_; kvsrc[3] = Vl_;

    const int nch  = 2 * (qt + 1);
    const int r_lo = tid >> 3;
    const int ch8  = tid & 7;

    // ---- prologue: Q (stage 0) and chunk 0 (stage 1) in flight together ----
    {
        const int r  = tid >> 1;
        const int c4 = (tid & 1) * 4;
        const size_t gq = ((size_t)(b * S_LEN + q0 + r)) * D_MODEL + hbase;
        const uint32_t d0 = smem + ((r >= 64) ? KV_TILE : 0) + (r & 63) * APITCH;
        #pragma unroll
        for (int j = 0; j < 4; j++) {
            cp_async16(d0 + (c4 + j) * 16, Qh_ + gq + (c4 + j) * 8);
            cp_async16(d0 + 2 * KV_TILE + (c4 + j) * 16, Ql_ + gq + (c4 + j) * 8);
        }
        CP_COMMIT();
    }
    {
        const uint32_t sb = smem + ASTAGE;   // chunk 0 -> stage 1
        #pragma unroll
        for (int i = 0; i < 8; i++) {
            const int tile = i >> 1;
            const int r    = ((i & 1) << 5) + r_lo;
            const __nv_bfloat16* gp =
                kvsrc[tile] + ((size_t)(b * S_LEN + r)) * D_MODEL + hbase + ch8 * 8;
            cp_async16(sb + tile * KV_TILE + r * APITCH + ch8 * 16, gp);
        }
        CP_COMMIT();
    }
    CP_WAIT(1);        // Q group done (chunk 0 may still be in flight)
    __syncthreads();

    uint32_t qh[4][4], ql[4][4];
    {
        const uint32_t qtb = smem + ((w >= 4) ? KV_TILE : 0) + (w & 3) * 16 * APITCH;
        #pragma unroll
        for (int ks = 0; ks < 4; ks++) {
            LDSM4(qh[ks], qtb + ks * 32 + aoff);
            LDSM4(ql[ks], qtb + 2 * KV_TILE + ks * 32 + aoff);
        }
    }
    __syncthreads();   // Q consumed; stage 0 free

    float o[8][4];
    #pragma unroll
    for (int nt = 0; nt < 8; nt++)
        #pragma unroll
        for (int e = 0; e < 4; e++) o[nt][e] = 0.f;
    float mi0 = -1e30f, mi1 = -1e30f, li0 = 0.f, li1 = 0.f;

    const int qmaxw = q0 + w * 16 + 15;   // max query row for this warp

    for (int c = 0; c < nch; c++) {
        if (c + 1 < nch) {
            const uint32_t sb = smem + (c & 1) * ASTAGE;   // chunk c+1 -> stage c&1
            const int k0 = (c + 1) * 64;
            #pragma unroll
            for (int i = 0; i < 8; i++) {
                const int tile = i >> 1;
                const int r    = ((i & 1) << 5) + r_lo;
                const __nv_bfloat16* gp =
                    kvsrc[tile] + ((size_t)(b * S_LEN + k0 + r)) * D_MODEL + hbase + ch8 * 8;
                cp_async16(sb + tile * KV_TILE + r * APITCH + ch8 * 16, gp);
            }
            CP_COMMIT();
            CP_WAIT(1);
        } else {
            CP_WAIT(0);
        }
        __syncthreads();

        const int c0 = c * 64;
        const bool diag = (c0 >= q0);
        const uint32_t sb  = smem + ((c + 1) & 1) * ASTAGE;
        const uint32_t Khs = sb;
        const uint32_t Kls = sb + KV_TILE;
        const uint32_t Vhs = sb + 2 * KV_TILE;
        const uint32_t Vls = sb + 3 * KV_TILE;

        float s[8][4];
        #pragma unroll
        for (int nt = 0; nt < 8; nt++)
            #pragma unroll
            for (int e = 0; e < 4; e++) s[nt][e] = 0.f;

        #pragma unroll
        for (int ks = 0; ks < 4; ks++) {
            uint32_t kh[4][4], kl[4][4];
            #pragma unroll
            for (int p = 0; p < 4; p++) {
                if (!diag || c0 + 16 * p <= qmaxw) {
                    LDSM4(kh[p], Khs + p * 16 * APITCH + ks * 32 + boff);
                    LDSM4(kl[p], Kls + p * 16 * APITCH + ks * 32 + boff);
                }
            }
            #pragma unroll
            for (int nt = 0; nt < 8; nt++) {
                if (!diag || c0 + 8 * nt <= qmaxw) {
                    const int p = nt >> 1;
                    const int q = nt & 1;
                    MMA16816(s[nt], qh[ks], kh[p][q], kh[p][q + 2]);
                    MMA16816(s[nt], ql[ks], kh[p][q], kh[p][q + 2]);
                    MMA16816(s[nt], qh[ks], kl[p][q], kl[p][q + 2]);
                }
            }
        }

        if (diag) {
            const int qr0 = q0 + w * 16 + (lane >> 2);
            #pragma unroll
            for (int nt = 0; nt < 8; nt++)
                #pragma unroll
                for (int e = 0; e < 4; e++) {
                    const int key = c0 + nt * 8 + 2 * (lane & 3) + (e & 1);
                    const int qr  = qr0 + (e >> 1) * 8;
                    if (key > qr) s[nt][e] = -1e30f;
                }
        }

        float rmax0 = -1e30f, rmax1 = -1e30f;
        #pragma unroll
        for (int nt = 0; nt < 8; nt++) {
            rmax0 = fmaxf(rmax0, fmaxf(s[nt][0], s[nt][1]));
            rmax1 = fmaxf(rmax1, fmaxf(s[nt][2], s[nt][3]));
        }
        rmax0 = fmaxf(rmax0, __shfl_xor_sync(0xffffffffu, rmax0, 1));
        rmax0 = fmaxf(rmax0, __shfl_xor_sync(0xffffffffu, rmax0, 2));
        rmax1 = fmaxf(rmax1, __shfl_xor_sync(0xffffffffu, rmax1, 1));
        rmax1 = fmaxf(rmax1, __shfl_xor_sync(0xffffffffu, rmax1, 2));

        const float mnew0 = fmaxf(mi0, rmax0);
        const float mnew1 = fmaxf(mi1, rmax1);
        const float alpha0 = __expf(mi0 - mnew0);
        const float alpha1 = __expf(mi1 - mnew1);
        mi0 = mnew0; mi1 = mnew1;

        float rsum0 = 0.f, rsum1 = 0.f;
        #pragma unroll
        for (int nt = 0; nt < 8; nt++) {
            s[nt][0] = __expf(s[nt][0] - mnew0);
            s[nt][1] = __expf(s[nt][1] - mnew0);
            s[nt][2] = __expf(s[nt][2] - mnew1);
            s[nt][3] = __expf(s[nt][3] - mnew1);
            rsum0 += s[nt][0] + s[nt][1];
            rsum1 += s[nt][2] + s[nt][3];
        }
        rsum0 += __shfl_xor_sync(0xffffffffu, rsum0, 1);
        rsum0 += __shfl_xor_sync(0xffffffffu, rsum0, 2);
        rsum1 += __shfl_xor_sync(0xffffffffu, rsum1, 1);
        rsum1 += __shfl_xor_sync(0xffffffffu, rsum1, 2);
        li0 = li0 * alpha0 + rsum0;
        li1 = li1 * alpha1 + rsum1;

        #pragma unroll
        for (int nt = 0; nt < 8; nt++) {
            o[nt][0] *= alpha0; o[nt][1] *= alpha0;
            o[nt][2] *= alpha1; o[nt][3] *= alpha1;
        }

        #pragma unroll
        for (int kb = 0; kb < 4; kb++) {
            if (!diag || c0 + 16 * kb <= qmaxw) {
                uint32_t ph[4], pl[4];
                {
                    const float* s0 = s[2 * kb];
                    const float* s1 = s[2 * kb + 1];
                    float h00 = bf_round(s0[0]), h01 = bf_round(s0[1]);
                    float h02 = bf_round(s0[2]), h03 = bf_round(s0[3]);
                    float h10 = bf_round(s1[0]), h11 = bf_round(s1[1]);
                    float h12 = bf_round(s1[2]), h13 = bf_round(s1[3]);
                    ph[0] = bf2x(s0[1], s0[0]);
                    ph[1] = bf2x(s0[3], s0[2]);
                    ph[2] = bf2x(s1[1], s1[0]);
                    ph[3] = bf2x(s1[3], s1[2]);
                    pl[0] = bf2x(s0[1] - h01, s0[0] - h00);
                    pl[1] = bf2x(s0[3] - h03, s0[2] - h02);
                    pl[2] = bf2x(s1[1] - h11, s1[0] - h10);
                    pl[3] = bf2x(s1[3] - h13, s1[2] - h12);
                }
                #pragma unroll
                for (int dt = 0; dt < 4; dt++) {
                    uint32_t vh[4], vl[4];
                    LDSM4T(vh, Vhs + kb * 16 * APITCH + dt * 32 + voff);
                    LDSM4T(vl, Vls + kb * 16 * APITCH + dt * 32 + voff);
                    #pragma unroll
                    for (int q = 0; q < 2; q++) {
                        const int nt = dt * 2 + q;
                        MMA16816(o[nt], ph, vh[2 * q], vh[2 * q + 1]);
                        MMA16816(o[nt], pl, vh[2 * q], vh[2 * q + 1]);
                        MMA16816(o[nt], ph, vl[2 * q], vl[2 * q + 1]);
                    }
                }
            }
        }
        __syncthreads();
    }

    // ---- epilogue: normalize, fused bf16 hi/lo split store ----
    const float inv0 = 1.f / li0;
    const float inv1 = 1.f / li1;
    const int qr0 = q0 + w * 16 + (lane >> 2);
    const int cb  = hbase + 2 * (lane & 3);
    #pragma unroll
    for (int nt = 0; nt < 8; nt++) {
        const float a0 = o[nt][0] * inv0, a1 = o[nt][1] * inv0;
        const float a2 = o[nt][2] * inv1, a3 = o[nt][3] * inv1;
        const float h0 = bf_round(a0), h1 = bf_round(a1);
        const float h2 = bf_round(a2), h3 = bf_round(a3);
        const size_t i0 = ((size_t)(b * S_LEN + qr0)) * D_MODEL + cb + nt * 8;
        const size_t i1 = ((size_t)(b * S_LEN + qr0 + 8)) * D_MODEL + cb + nt * 8;
        *(uint32_t*)&AOh[i0] = bf2x(a1, a0);
        *(uint32_t*)&AOl[i0] = bf2x(a1 - h1, a0 - h0);
        *(uint32_t*)&AOh[i1] = bf2x(a3, a2);
        *(uint32_t*)&AOl[i1] = bf2x(a3 - h3, a2 - h2);
    }
}

// ---------------------------------------------------------------------------
// Launch
// ---------------------------------------------------------------------------
extern "C" void kernel_launch(void* const* d_in, const int* in_sizes, int n_in,
                              void* d_out, int out_size)
{
    const float* x  = (const float*)d_in[0];
    float* out = (float*)d_out;

    __nv_bfloat16 *pxh, *pxl, *pwh, *pwl;
    __nv_bfloat16 *pqh, *pql, *pkh, *pkl, *pvh, *pvl, *paoh, *paol;
    cudaGetSymbolAddress((void**)&pxh,  g_xh);
    cudaGetSymbolAddress((void**)&pxl,  g_xl);
    cudaGetSymbolAddress((void**)&pwh,  g_wh);
    cudaGetSymbolAddress((void**)&pwl,  g_wl);
    cudaGetSymbolAddress((void**)&pqh,  g_qh);
    cudaGetSymbolAddress((void**)&pql,  g_ql);
    cudaGetSymbolAddress((void**)&pkh,  g_kh);
    cudaGetSymbolAddress((void**)&pkl,  g_kl);
    cudaGetSymbolAddress((void**)&pvh,  g_vh);
    cudaGetSymbolAddress((void**)&pvl,  g_vl);
    cudaGetSymbolAddress((void**)&paoh, g_aoh);
    cudaGetSymbolAddress((void**)&paol, g_aol);

    cudaFuncSetAttribute(gemm_bf16x3,
                         cudaFuncAttributeMaxDynamicSharedMemorySize, GSMEM3);
    cudaFuncSetAttribute(attn_mma,
                         cudaFuncAttributeMaxDynamicSharedMemorySize, ASMEM);

    const int n4e = MROWS * KDIM / 4;
    const int n4w = KDIM * NDIM / 4;

    // 1) split external inputs (x; all 4 weights in one launch)
    split_bf16<<<(n4e + 255) / 256, 256>>>(x, pxh, pxl, n4e);
    split_w4<<<(4 * n4w + 255) / 256, 256>>>(
        (const float*)d_in[1], (const float*)d_in[2],
        (const float*)d_in[3], (const float*)d_in[4],
        pwh, pwl, n4w);

    // 2) fused Q/K/V projection (one launch, 384 CTAs)
    dim3 qkv_grid(12, MROWS / 128);
    gemm_bf16x3<<<qkv_grid, 256, GSMEM3>>>(pxh, pxl, pwh, pwl,
        (float*)nullptr, pqh, pql, pkh, pkl, pvh, pvl, 1);

    // 3) tensor-core causal attention (writes aoh/aol directly)
    dim3 agrid(NQT, NHEAD, B_SZ);
    attn_mma<<<agrid, 256, ASMEM>>>(pqh, pql, pkh, pkl, pvh, pvl, paoh, paol);

    // 4) output projection -> fp32 out
    dim3 ogrid(4, MROWS / 128);
    gemm_bf16x3<<<ogrid, 256, GSMEM3>>>(paoh, paol,
        pwh + 3 * (size_t)KDIM * NDIM, pwl + 3 * (size_t)KDIM * NDIM,
        out, (__nv_bfloat16*)nullptr, (__nv_bfloat16*)nullptr,
        (__nv_bfloat16*)nullptr, (__nv_bfloat16*)nullptr,
        (__nv_bfloat16*)nullptr, (__nv_bfloat16*)nullptr, 0);
}

// round 11
// speedup vs baseline: 1.0017x; 1.0017x over previous
#include <cuda_runtime.h>
#include <cuda_bf16.h>
#include <cstdint>
#include <math.h>

// ---------------------------------------------------------------------------
// Problem constants
// ---------------------------------------------------------------------------
#define B_SZ    2
#define S_LEN   2048
#define D_MODEL 1024
#define NHEAD   16
#define DKH     64
#define MROWS   4096
#define KDIM    1024
#define NDIM    1024
#define NQT64   (S_LEN / 64)      // 32 q-tiles of 64 rows

// ---------------------------------------------------------------------------
// Scratch (device globals)
// ---------------------------------------------------------------------------
__device__ __align__(16) __nv_bfloat16 g_xh [MROWS * KDIM];
__device__ __align__(16) __nv_bfloat16 g_xl [MROWS * KDIM];
__device__ __align__(16) __nv_bfloat16 g_wh [4 * KDIM * NDIM];
__device__ __align__(16) __nv_bfloat16 g_wl [4 * KDIM * NDIM];
__device__ __align__(16) __nv_bfloat16 g_qh [MROWS * D_MODEL];
__device__ __align__(16) __nv_bfloat16 g_ql [MROWS * D_MODEL];
__device__ __align__(16) __nv_bfloat16 g_kh [MROWS * D_MODEL];
__device__ __align__(16) __nv_bfloat16 g_kl [MROWS * D_MODEL];
__device__ __align__(16) __nv_bfloat16 g_vh [MROWS * D_MODEL];
__device__ __align__(16) __nv_bfloat16 g_vl [MROWS * D_MODEL];
__device__ __align__(16) __nv_bfloat16 g_aoh[MROWS * D_MODEL];
__device__ __align__(16) __nv_bfloat16 g_aol[MROWS * D_MODEL];

// ---------------------------------------------------------------------------
// PTX helpers (sm_80-era, valid at compute_100)
// ---------------------------------------------------------------------------
__device__ __forceinline__ uint32_t smem_u32(const void* p) {
    uint32_t a;
    asm("{ .reg .u64 t; cvta.to.shared.u64 t, %1; cvt.u32.u64 %0, t; }"
        : "=r"(a) : "l"(p));
    return a;
}

__device__ __forceinline__ void cp_async16(uint32_t dst, const void* src) {
    asm volatile("cp.async.cg.shared.global [%0], [%1], 16;"
                 :: "r"(dst), "l"(src) : "memory");
}
#define CP_COMMIT() asm volatile("cp.async.commit_group;" ::: "memory")
#define CP_WAIT(n)  asm volatile("cp.async.wait_group %0;" :: "n"(n) : "memory")

#define LDSM4(r, addr) \
    asm volatile("ldmatrix.sync.aligned.m8n8.x4.shared.b16 {%0,%1,%2,%3}, [%4];" \
                 : "=r"((r)[0]), "=r"((r)[1]), "=r"((r)[2]), "=r"((r)[3]) : "r"(addr))

#define LDSM4T(r, addr) \
    asm volatile("ldmatrix.sync.aligned.m8n8.x4.trans.shared.b16 {%0,%1,%2,%3}, [%4];" \
                 : "=r"((r)[0]), "=r"((r)[1]), "=r"((r)[2]), "=r"((r)[3]) : "r"(addr))

#define MMA16816(d, a, b0v, b1v) \
    asm volatile("mma.sync.aligned.m16n8k16.row.col.f32.bf16.bf16.f32 " \
                 "{%0,%1,%2,%3}, {%4,%5,%6,%7}, {%8,%9}, {%0,%1,%2,%3};" \
                 : "+f"((d)[0]), "+f"((d)[1]), "+f"((d)[2]), "+f"((d)[3]) \
                 : "r"((a)[0]), "r"((a)[1]), "r"((a)[2]), "r"((a)[3]), \
                   "r"(b0v), "r"(b1v))

__device__ __forceinline__ uint32_t bf2x(float hi, float lo) {
    uint32_t d;
    asm("cvt.rn.bf16x2.f32 %0, %1, %2;" : "=r"(d) : "f"(hi), "f"(lo));
    return d;
}
__device__ __forceinline__ float bf_round(float x) {
    return __bfloat162float(__float2bfloat16_rn(x));
}

// ---------------------------------------------------------------------------
// fp32 -> bf16 hi/lo splits (x; and all 4 weights in one launch)
// ---------------------------------------------------------------------------
__global__ __launch_bounds__(256)
void split_bf16(const float* __restrict__ in, __nv_bfloat16* __restrict__ hi,
                __nv_bfloat16* __restrict__ lo, int n4)
{
    int i = blockIdx.x * blockDim.x + threadIdx.x;
    if (i >= n4) return;
    float4 v = ((const float4*)in)[i];
    float f[4] = {v.x, v.y, v.z, v.w};
    unsigned short hs[4], ls[4];
    #pragma unroll
    for (int j = 0; j < 4; j++) {
        __nv_bfloat16 h = __float2bfloat16_rn(f[j]);
        float r = f[j] - __bfloat162float(h);
        __nv_bfloat16 l = __float2bfloat16_rn(r);
        hs[j] = __bfloat16_as_ushort(h);
        ls[j] = __bfloat16_as_ushort(l);
    }
    ((ushort4*)hi)[i] = make_ushort4(hs[0], hs[1], hs[2], hs[3]);
    ((ushort4*)lo)[i] = make_ushort4(ls[0], ls[1], ls[2], ls[3]);
}

__global__ __launch_bounds__(256)
void split_w4(const float* __restrict__ w0, const float* __restrict__ w1,
              const float* __restrict__ w2, const float* __restrict__ w3,
              __nv_bfloat16* __restrict__ hi, __nv_bfloat16* __restrict__ lo,
              int n4w)
{
    int i = blockIdx.x * blockDim.x + threadIdx.x;
    if (i >= 4 * n4w) return;
    const int m = i / n4w;
    const int j = i - m * n4w;
    const float* src = (m == 0) ? w0 : (m == 1) ? w1 : (m == 2) ? w2 : w3;
    float4 v = ((const float4*)src)[j];
    float f[4] = {v.x, v.y, v.z, v.w};
    unsigned short hs[4], ls[4];
    #pragma unroll
    for (int jj = 0; jj < 4; jj++) {
        __nv_bfloat16 h = __float2bfloat16_rn(f[jj]);
        float r = f[jj] - __bfloat162float(h);
        __nv_bfloat16 l = __float2bfloat16_rn(r);
        hs[jj] = __bfloat16_as_ushort(h);
        ls[jj] = __bfloat16_as_ushort(l);
    }
    ((ushort4*)hi)[i] = make_ushort4(hs[0], hs[1], hs[2], hs[3]);
    ((ushort4*)lo)[i] = make_ushort4(ls[0], ls[1], ls[2], ls[3]);
}

// ---------------------------------------------------------------------------
// bf16x3-split GEMM via mma.sync:  C = A B^T (NT), 128x256x32 CTA tile.
// 256 threads, 8 warps (2m x 4n), warp tile 64x64. 2-stage cp.async pipeline
// (known-good R8 configuration).
// ---------------------------------------------------------------------------
#define ATB     10240                 // 128 * 80
#define BTB     20480                 // 256 * 80
#define STG2    (2 * ATB + 2 * BTB)   // 61440
#define GSMEM2  (2 * STG2)            // 122880
#define KT      (KDIM / 32)           // 32

__global__ __launch_bounds__(256, 1)
void gemm_bf16x3(const __nv_bfloat16* __restrict__ Agh,
                 const __nv_bfloat16* __restrict__ Agl,
                 const __nv_bfloat16* __restrict__ Bgh,
                 const __nv_bfloat16* __restrict__ Bgl,
                 float* __restrict__ Cf,
                 __nv_bfloat16* __restrict__ Ch,
                 __nv_bfloat16* __restrict__ Cl,
                 float scale)
{
    extern __shared__ __align__(128) char smem_raw[];
    const uint32_t smem = smem_u32(smem_raw);

    const int tid    = threadIdx.x;
    const int lane   = tid & 31;
    const int wid    = tid >> 5;
    const int warp_m = wid & 1;
    const int warp_n = wid >> 1;
    const int row0   = blockIdx.y * 128;
    const int col0   = blockIdx.x * 256;

    const uint32_t aoff = (uint32_t)((lane & 15) * 80 + ((lane >> 4) << 4));
    const uint32_t boff = (uint32_t)((((lane >> 3) & 1) * 8 + (lane & 7)) * 80 +
                                     ((lane >> 4) << 4));

    float acc[4][8][4];
    #pragma unroll
    for (int mt = 0; mt < 4; mt++)
        #pragma unroll
        for (int nt = 0; nt < 8; nt++)
            #pragma unroll
            for (int q = 0; q < 4; q++) acc[mt][nt][q] = 0.f;

    const int r_lo = tid >> 2;
    const int k16  = tid & 3;

    #define LOAD_STAGE(sb, k0)                                                  \
    do {                                                                        \
        const size_t kofs = (size_t)(k0) + k16 * 8;                             \
        _Pragma("unroll")                                                       \
        for (int rr = 0; rr < 2; rr++) {                                        \
            const int r = r_lo + rr * 64;                                       \
            cp_async16((sb) + r * 80 + k16 * 16,                                \
                       Agh + (size_t)(row0 + r) * KDIM + kofs);                 \
            cp_async16((sb) + ATB + r * 80 + k16 * 16,                          \
                       Agl + (size_t)(row0 + r) * KDIM + kofs);                 \
        }                                                                       \
        _Pragma("unroll")                                                       \
        for (int rr = 0; rr < 4; rr++) {                                        \
            const int r = r_lo + rr * 64;                                       \
            cp_async16((sb) + 2 * ATB + r * 80 + k16 * 16,                      \
                       Bgh + (size_t)(col0 + r) * KDIM + kofs);                 \
            cp_async16((sb) + 2 * ATB + BTB + r * 80 + k16 * 16,                \
                       Bgl + (size_t)(col0 + r) * KDIM + kofs);                 \
        }                                                                       \
    } while (0)

    LOAD_STAGE(smem, 0);
    CP_COMMIT();

    for (int t = 0; t < KT; t++) {
        const int cur = t & 1;
        if (t + 1 < KT) {
            const uint32_t sb = smem + ((t + 1) & 1) * STG2;
            LOAD_STAGE(sb, (t + 1) * 32);
            CP_COMMIT();
            CP_WAIT(1);
        } else {
            CP_WAIT(0);
        }
        __syncthreads();

        const uint32_t sb  = smem + cur * STG2;
        const uint32_t Ahs = sb;
        const uint32_t Bhs = sb + 2 * ATB;

        #pragma unroll
        for (int kk = 0; kk < 2; kk++) {
            const uint32_t kkb = kk * 32;
            uint32_t ah[4][4];
            uint32_t al[4][4];
            uint32_t bh[4][4];
            uint32_t bl[4][4];
            #pragma unroll
            for (int mt = 0; mt < 4; mt++) {
                const uint32_t ad = Ahs + (warp_m * 64 + mt * 16) * 80 + kkb + aoff;
                LDSM4(ah[mt], ad);
                LDSM4(al[mt], ad + ATB);
            }
            #pragma unroll
            for (int p = 0; p < 4; p++) {
                const uint32_t bd = Bhs + (warp_n * 64 + p * 16) * 80 + kkb + boff;
                LDSM4(bh[p], bd);
                LDSM4(bl[p], bd + BTB);
            }
            #pragma unroll
            for (int mt = 0; mt < 4; mt++)
                #pragma unroll
                for (int nt = 0; nt < 8; nt++) {
                    float* d = acc[mt][nt];
                    const int p = nt >> 1;
                    const int q = nt & 1;
                    MMA16816(d, ah[mt], bh[p][q], bh[p][q + 2]);
                    MMA16816(d, ah[mt], bl[p][q], bl[p][q + 2]);
                    MMA16816(d, al[mt], bh[p][q], bh[p][q + 2]);
                }
        }
        __syncthreads();
    }
    #undef LOAD_STAGE

    // ---- epilogue ----
    const int rbase = row0 + warp_m * 64 + (lane >> 2);
    const int cbase = col0 + warp_n * 64 + (lane & 3) * 2;
    #pragma unroll
    for (int mt = 0; mt < 4; mt++) {
        #pragma unroll
        for (int nt = 0; nt < 8; nt++) {
            const int r = rbase + mt * 16;
            const int c = cbase + nt * 8;
            const float v0 = acc[mt][nt][0] * scale;
            const float v1 = acc[mt][nt][1] * scale;
            const float v2 = acc[mt][nt][2] * scale;
            const float v3 = acc[mt][nt][3] * scale;
            if (Cf) {
                *(float2*)&Cf[(size_t)r * NDIM + c]       = make_float2(v0, v1);
                *(float2*)&Cf[(size_t)(r + 8) * NDIM + c] = make_float2(v2, v3);
            }
            if (Ch) {
                const float h0 = bf_round(v0), h1 = bf_round(v1);
                const float h2 = bf_round(v2), h3 = bf_round(v3);
                *(uint32_t*)&Ch[(size_t)r * NDIM + c]       = bf2x(v1, v0);
                *(uint32_t*)&Cl[(size_t)r * NDIM + c]       = bf2x(v1 - h1, v0 - h0);
                *(uint32_t*)&Ch[(size_t)(r + 8) * NDIM + c] = bf2x(v3, v2);
                *(uint32_t*)&Cl[(size_t)(r + 8) * NDIM + c] = bf2x(v3 - h3, v2 - h2);
            }
        }
    }
}

// ---------------------------------------------------------------------------
// Tensor-core causal flash attention, bf16x3 split.
// 128 threads (4 warps), 64-row q-tile, __launch_bounds__(128,2) so TWO
// independent CTAs share each SM (barriers/softmax in one overlap MMAs in
// the other). Chunk c lives in smem stage (c+1)&1; chunk 0 prefetches
// during the Q load. Warp-uniform causal skip on the diagonal chunk.
// ---------------------------------------------------------------------------
#define APITCH  144
#define KV_TILE (64 * APITCH)
#define ASTAGE  (4 * KV_TILE)
#define ASMEM   (2 * ASTAGE)        // 73728

__global__ __launch_bounds__(128, 2)
void attn_mma(const __nv_bfloat16* __restrict__ Qh_, const __nv_bfloat16* __restrict__ Ql_,
              const __nv_bfloat16* __restrict__ Kh_, const __nv_bfloat16* __restrict__ Kl_,
              const __nv_bfloat16* __restrict__ Vh_, const __nv_bfloat16* __restrict__ Vl_,
              __nv_bfloat16* __restrict__ AOh, __nv_bfloat16* __restrict__ AOl)
{
    extern __shared__ __align__(128) char smx[];
    const uint32_t smem = smem_u32(smx);
    const int tid  = threadIdx.x;
    const int lane = tid & 31;
    const int w    = tid >> 5;                 // 0..3
    const int qt   = (NQT64 - 1) - blockIdx.x; // heavy tiles first
    const int h    = blockIdx.y;
    const int b    = blockIdx.z;
    const int q0   = qt * 64;
    const int hbase = h * 64;

    const uint32_t aoff = (uint32_t)((lane & 15) * APITCH + ((lane >> 4) << 4));
    const uint32_t boff = (uint32_t)((((lane >> 3) & 1) * 8 + (lane & 7)) * APITCH +
                                     ((lane >> 4) << 4));
    const uint32_t voff = aoff;

    const __nv_bfloat16* kvsrc[4];
    kvsrc[0] = Kh_; kvsrc[1] = Kl_; kvsrc[2] = Vh_; kvsrc[3] = Vl_;

    const int nch = qt + 1;

    // ---- prologue: Q (stage 0) and chunk 0 (stage 1) in flight together ----
    {
        const int r  = tid >> 1;               // 0..63
        const int c4 = (tid & 1) * 4;
        const size_t gq = ((size_t)(b * S_LEN + q0 + r)) * D_MODEL + hbase;
        const uint32_t d0 = smem + r * APITCH;
        #pragma unroll
        for (int j = 0; j < 4; j++) {
            cp_async16(d0 + (c4 + j) * 16, Qh_ + gq + (c4 + j) * 8);
            cp_async16(d0 + 2 * KV_TILE + (c4 + j) * 16, Ql_ + gq + (c4 + j) * 8);
        }
        CP_COMMIT();
    }
    {
        const uint32_t sb = smem + ASTAGE;     // chunk 0 -> stage 1
        #pragma unroll
        for (int i = 0; i < 16; i++) {
            const int tile = i >> 2;
            const int r    = ((i & 3) << 4) + (tid >> 3);
            const __nv_bfloat16* gp =
                kvsrc[tile] + ((size_t)(b * S_LEN + r)) * D_MODEL + hbase + (tid & 7) * 8;
            cp_async16(sb + tile * KV_TILE + r * APITCH + (tid & 7) * 16, gp);
        }
        CP_COMMIT();
    }
    CP_WAIT(1);
    __syncthreads();

    uint32_t qh[4][4], ql[4][4];
    {
        const uint32_t qtb = smem + (w * 16) * APITCH;
        #pragma unroll
        for (int ks = 0; ks < 4; ks++) {
            LDSM4(qh[ks], qtb + ks * 32 + aoff);
            LDSM4(ql[ks], qtb + 2 * KV_TILE + ks * 32 + aoff);
        }
    }
    __syncthreads();   // Q consumed; stage 0 free

    float o[8][4];
    #pragma unroll
    for (int nt = 0; nt < 8; nt++)
        #pragma unroll
        for (int e = 0; e < 4; e++) o[nt][e] = 0.f;
    float mi0 = -1e30f, mi1 = -1e30f, li0 = 0.f, li1 = 0.f;

    const int qmaxw = q0 + w * 16 + 15;

    for (int c = 0; c < nch; c++) {
        if (c + 1 < nch) {
            const uint32_t sb = smem + (c & 1) * ASTAGE;
            const int k0 = (c + 1) * 64;
            #pragma unroll
            for (int i = 0; i < 16; i++) {
                const int tile = i >> 2;
                const int r    = ((i & 3) << 4) + (tid >> 3);
                const __nv_bfloat16* gp =
                    kvsrc[tile] + ((size_t)(b * S_LEN + k0 + r)) * D_MODEL + hbase + (tid & 7) * 8;
                cp_async16(sb + tile * KV_TILE + r * APITCH + (tid & 7) * 16, gp);
            }
            CP_COMMIT();
            CP_WAIT(1);
        } else {
            CP_WAIT(0);
        }
        __syncthreads();

        const int c0 = c * 64;
        const bool diag = (c0 >= q0);
        const uint32_t sb  = smem + ((c + 1) & 1) * ASTAGE;
        const uint32_t Khs = sb;
        const uint32_t Kls = sb + KV_TILE;
        const uint32_t Vhs = sb + 2 * KV_TILE;
        const uint32_t Vls = sb + 3 * KV_TILE;

        float s[8][4];
        #pragma unroll
        for (int nt = 0; nt < 8; nt++)
            #pragma unroll
            for (int e = 0; e < 4; e++) s[nt][e] = 0.f;

        #pragma unroll
        for (int ks = 0; ks < 4; ks++) {
            uint32_t kh[4][4], kl[4][4];
            #pragma unroll
            for (int p = 0; p < 4; p++) {
                if (!diag || c0 + 16 * p <= qmaxw) {
                    LDSM4(kh[p], Khs + p * 16 * APITCH + ks * 32 + boff);
                    LDSM4(kl[p], Kls + p * 16 * APITCH + ks * 32 + boff);
                }
            }
            #pragma unroll
            for (int nt = 0; nt < 8; nt++) {
                if (!diag || c0 + 8 * nt <= qmaxw) {
                    const int p = nt >> 1;
                    const int q = nt & 1;
                    MMA16816(s[nt], qh[ks], kh[p][q], kh[p][q + 2]);
                    MMA16816(s[nt], ql[ks], kh[p][q], kh[p][q + 2]);
                    MMA16816(s[nt], qh[ks], kl[p][q], kl[p][q + 2]);
                }
            }
        }

        if (diag) {
            const int qr0 = q0 + w * 16 + (lane >> 2);
            #pragma unroll
            for (int nt = 0; nt < 8; nt++)
                #pragma unroll
                for (int e = 0; e < 4; e++) {
                    const int key = c0 + nt * 8 + 2 * (lane & 3) + (e & 1);
                    const int qr  = qr0 + (e >> 1) * 8;
                    if (key > qr) s[nt][e] = -1e30f;
                }
        }

        float rmax0 = -1e30f, rmax1 = -1e30f;
        #pragma unroll
        for (int nt = 0; nt < 8; nt++) {
            rmax0 = fmaxf(rmax0, fmaxf(s[nt][0], s[nt][1]));
            rmax1 = fmaxf(rmax1, fmaxf(s[nt][2], s[nt][3]));
        }
        rmax0 = fmaxf(rmax0, __shfl_xor_sync(0xffffffffu, rmax0, 1));
        rmax0 = fmaxf(rmax0, __shfl_xor_sync(0xffffffffu, rmax0, 2));
        rmax1 = fmaxf(rmax1, __shfl_xor_sync(0xffffffffu, rmax1, 1));
        rmax1 = fmaxf(rmax1, __shfl_xor_sync(0xffffffffu, rmax1, 2));

        const float mnew0 = fmaxf(mi0, rmax0);
        const float mnew1 = fmaxf(mi1, rmax1);
        const float alpha0 = __expf(mi0 - mnew0);
        const float alpha1 = __expf(mi1 - mnew1);
        mi0 = mnew0; mi1 = mnew1;

        float rsum0 = 0.f, rsum1 = 0.f;
        #pragma unroll
        for (int nt = 0; nt < 8; nt++) {
            s[nt][0] = __expf(s[nt][0] - mnew0);
            s[nt][1] = __expf(s[nt][1] - mnew0);
            s[nt][2] = __expf(s[nt][2] - mnew1);
            s[nt][3] = __expf(s[nt][3] - mnew1);
            rsum0 += s[nt][0] + s[nt][1];
            rsum1 += s[nt][2] + s[nt][3];
        }
        rsum0 += __shfl_xor_sync(0xffffffffu, rsum0, 1);
        rsum0 += __shfl_xor_sync(0xffffffffu, rsum0, 2);
        rsum1 += __shfl_xor_sync(0xffffffffu, rsum1, 1);
        rsum1 += __shfl_xor_sync(0xffffffffu, rsum1, 2);
        li0 = li0 * alpha0 + rsum0;
        li1 = li1 * alpha1 + rsum1;

        #pragma unroll
        for (int nt = 0; nt < 8; nt++) {
            o[nt][0] *= alpha0; o[nt][1] *= alpha0;
            o[nt][2] *= alpha1; o[nt][3] *= alpha1;
        }

        #pragma unroll
        for (int kb = 0; kb < 4; kb++) {
            if (!diag || c0 + 16 * kb <= qmaxw) {
                uint32_t ph[4], pl[4];
                {
                    const float* s0 = s[2 * kb];
                    const float* s1 = s[2 * kb + 1];
                    float h00 = bf_round(s0[0]), h01 = bf_round(s0[1]);
                    float h02 = bf_round(s0[2]), h03 = bf_round(s0[3]);
                    float h10 = bf_round(s1[0]), h11 = bf_round(s1[1]);
                    float h12 = bf_round(s1[2]), h13 = bf_round(s1[3]);
                    ph[0] = bf2x(s0[1], s0[0]);
                    ph[1] = bf2x(s0[3], s0[2]);
                    ph[2] = bf2x(s1[1], s1[0]);
                    ph[3] = bf2x(s1[3], s1[2]);
                    pl[0] = bf2x(s0[1] - h01, s0[0] - h00);
                    pl[1] = bf2x(s0[3] - h03, s0[2] - h02);
                    pl[2] = bf2x(s1[1] - h11, s1[0] - h10);
                    pl[3] = bf2x(s1[3] - h13, s1[2] - h12);
                }
                #pragma unroll
                for (int dt = 0; dt < 4; dt++) {
                    uint32_t vh[4], vl[4];
                    LDSM4T(vh, Vhs + kb * 16 * APITCH + dt * 32 + voff);
                    LDSM4T(vl, Vls + kb * 16 * APITCH + dt * 32 + voff);
                    #pragma unroll
                    for (int q = 0; q < 2; q++) {
                        const int nt = dt * 2 + q;
                        MMA16816(o[nt], ph, vh[2 * q], vh[2 * q + 1]);
                        MMA16816(o[nt], pl, vh[2 * q], vh[2 * q + 1]);
                        MMA16816(o[nt], ph, vl[2 * q], vl[2 * q + 1]);
                    }
                }
            }
        }
        __syncthreads();
    }

    // ---- epilogue: normalize, fused bf16 hi/lo split store ----
    const float inv0 = 1.f / li0;
    const float inv1 = 1.f / li1;
    const int qr0 = q0 + w * 16 + (lane >> 2);
    const int cb  = hbase + 2 * (lane & 3);
    #pragma unroll
    for (int nt = 0; nt < 8; nt++) {
        const float a0 = o[nt][0] * inv0, a1 = o[nt][1] * inv0;
        const float a2 = o[nt][2] * inv1, a3 = o[nt][3] * inv1;
        const float h0 = bf_round(a0), h1 = bf_round(a1);
        const float h2 = bf_round(a2), h3 = bf_round(a3);
        const size_t i0 = ((size_t)(b * S_LEN + qr0)) * D_MODEL + cb + nt * 8;
        const size_t i1 = ((size_t)(b * S_LEN + qr0 + 8)) * D_MODEL + cb + nt * 8;
        *(uint32_t*)&AOh[i0] = bf2x(a1, a0);
        *(uint32_t*)&AOl[i0] = bf2x(a1 - h1, a0 - h0);
        *(uint32_t*)&AOh[i1] = bf2x(a3, a2);
        *(uint32_t*)&AOl[i1] = bf2x(a3 - h3, a2 - h2);
    }
}

// ---------------------------------------------------------------------------
// Launch
// ---------------------------------------------------------------------------
extern "C" void kernel_launch(void* const* d_in, const int* in_sizes, int n_in,
                              void* d_out, int out_size)
{
    const float* x  = (const float*)d_in[0];
    float* out = (float*)d_out;

    __nv_bfloat16 *pxh, *pxl, *pwh, *pwl;
    __nv_bfloat16 *pqh, *pql, *pkh, *pkl, *pvh, *pvl, *paoh, *paol;
    cudaGetSymbolAddress((void**)&pxh,  g_xh);
    cudaGetSymbolAddress((void**)&pxl,  g_xl);
    cudaGetSymbolAddress((void**)&pwh,  g_wh);
    cudaGetSymbolAddress((void**)&pwl,  g_wl);
    cudaGetSymbolAddress((void**)&pqh,  g_qh);
    cudaGetSymbolAddress((void**)&pql,  g_ql);
    cudaGetSymbolAddress((void**)&pkh,  g_kh);
    cudaGetSymbolAddress((void**)&pkl,  g_kl);
    cudaGetSymbolAddress((void**)&pvh,  g_vh);
    cudaGetSymbolAddress((void**)&pvl,  g_vl);
    cudaGetSymbolAddress((void**)&paoh, g_aoh);
    cudaGetSymbolAddress((void**)&paol, g_aol);

    cudaFuncSetAttribute(gemm_bf16x3,
                         cudaFuncAttributeMaxDynamicSharedMemorySize, GSMEM2);
    cudaFuncSetAttribute(attn_mma,
                         cudaFuncAttributeMaxDynamicSharedMemorySize, ASMEM);

    const int n4e = MROWS * KDIM / 4;
    const int n4w = KDIM * NDIM / 4;

    // 1) split external inputs (x; all 4 weights in one launch)
    split_bf16<<<(n4e + 255) / 256, 256>>>(x, pxh, pxl, n4e);
    split_w4<<<(4 * n4w + 255) / 256, 256>>>(
        (const float*)d_in[1], (const float*)d_in[2],
        (const float*)d_in[3], (const float*)d_in[4],
        pwh, pwl, n4w);

    // 2) Q/K/V projections with fused hi/lo split epilogue (Q scaled 1/8)
    dim3 ggrid(NDIM / 256, MROWS / 128);   // (4, 32)
    gemm_bf16x3<<<ggrid, 256, GSMEM2>>>(pxh, pxl,
        pwh + 0 * (size_t)KDIM * NDIM, pwl + 0 * (size_t)KDIM * NDIM,
        (float*)nullptr, pqh, pql, 0.125f);
    gemm_bf16x3<<<ggrid, 256, GSMEM2>>>(pxh, pxl,
        pwh + 1 * (size_t)KDIM * NDIM, pwl + 1 * (size_t)KDIM * NDIM,
        (float*)nullptr, pkh, pkl, 1.f);
    gemm_bf16x3<<<ggrid, 256, GSMEM2>>>(pxh, pxl,
        pwh + 2 * (size_t)KDIM * NDIM, pwl + 2 * (size_t)KDIM * NDIM,
        (float*)nullptr, pvh, pvl, 1.f);

    // 3) tensor-core causal attention (2 CTAs/SM)
    dim3 agrid(NQT64, NHEAD, B_SZ);        // (32, 16, 2)
    attn_mma<<<agrid, 128, ASMEM>>>(pqh, pql, pkh, pkl, pvh, pvl, paoh, paol);

    // 4) output projection -> fp32 out
    gemm_bf16x3<<<ggrid, 256, GSMEM2>>>(paoh, paol,
        pwh + 3 * (size_t)KDIM * NDIM, pwl + 3 * (size_t)KDIM * NDIM,
        out, (__nv_bfloat16*)nullptr, (__nv_bfloat16*)nullptr, 1.f);
}

// round 12
// speedup vs baseline: 1.0037x; 1.0020x over previous
#include <cuda_runtime.h>
#include <cuda_bf16.h>
#include <cstdint>
#include <math.h>

// ---------------------------------------------------------------------------
// Problem constants
// ---------------------------------------------------------------------------
#define B_SZ    2
#define S_LEN   2048
#define D_MODEL 1024
#define NHEAD   16
#define DKH     64
#define MROWS   4096
#define KDIM    1024
#define NDIM    1024
#define NQT64   (S_LEN / 64)      // 32 q-tiles of 64 rows

// ---------------------------------------------------------------------------
// Scratch (device globals)
// ---------------------------------------------------------------------------
__device__ __align__(16) __nv_bfloat16 g_xh [MROWS * KDIM];
__device__ __align__(16) __nv_bfloat16 g_xl [MROWS * KDIM];
__device__ __align__(16) __nv_bfloat16 g_wh [4 * KDIM * NDIM];
__device__ __align__(16) __nv_bfloat16 g_wl [4 * KDIM * NDIM];
__device__ __align__(16) __nv_bfloat16 g_qh [MROWS * D_MODEL];
__device__ __align__(16) __nv_bfloat16 g_ql [MROWS * D_MODEL];
__device__ __align__(16) __nv_bfloat16 g_kh [MROWS * D_MODEL];
__device__ __align__(16) __nv_bfloat16 g_kl [MROWS * D_MODEL];
__device__ __align__(16) __nv_bfloat16 g_vh [MROWS * D_MODEL];
__device__ __align__(16) __nv_bfloat16 g_vl [MROWS * D_MODEL];
__device__ __align__(16) __nv_bfloat16 g_aoh[MROWS * D_MODEL];
__device__ __align__(16) __nv_bfloat16 g_aol[MROWS * D_MODEL];

// ---------------------------------------------------------------------------
// PTX helpers (sm_80-era, valid at compute_100)
// ---------------------------------------------------------------------------
__device__ __forceinline__ uint32_t smem_u32(const void* p) {
    uint32_t a;
    asm("{ .reg .u64 t; cvta.to.shared.u64 t, %1; cvt.u32.u64 %0, t; }"
        : "=r"(a) : "l"(p));
    return a;
}

__device__ __forceinline__ void cp_async16(uint32_t dst, const void* src) {
    asm volatile("cp.async.cg.shared.global [%0], [%1], 16;"
                 :: "r"(dst), "l"(src) : "memory");
}
#define CP_COMMIT() asm volatile("cp.async.commit_group;" ::: "memory")
#define CP_WAIT(n)  asm volatile("cp.async.wait_group %0;" :: "n"(n) : "memory")

#define LDSM4(r, addr) \
    asm volatile("ldmatrix.sync.aligned.m8n8.x4.shared.b16 {%0,%1,%2,%3}, [%4];" \
                 : "=r"((r)[0]), "=r"((r)[1]), "=r"((r)[2]), "=r"((r)[3]) : "r"(addr))

#define LDSM4T(r, addr) \
    asm volatile("ldmatrix.sync.aligned.m8n8.x4.trans.shared.b16 {%0,%1,%2,%3}, [%4];" \
                 : "=r"((r)[0]), "=r"((r)[1]), "=r"((r)[2]), "=r"((r)[3]) : "r"(addr))

#define MMA16816(d, a, b0v, b1v) \
    asm volatile("mma.sync.aligned.m16n8k16.row.col.f32.bf16.bf16.f32 " \
                 "{%0,%1,%2,%3}, {%4,%5,%6,%7}, {%8,%9}, {%0,%1,%2,%3};" \
                 : "+f"((d)[0]), "+f"((d)[1]), "+f"((d)[2]), "+f"((d)[3]) \
                 : "r"((a)[0]), "r"((a)[1]), "r"((a)[2]), "r"((a)[3]), \
                   "r"(b0v), "r"(b1v))

__device__ __forceinline__ uint32_t bf2x(float hi, float lo) {
    uint32_t d;
    asm("cvt.rn.bf16x2.f32 %0, %1, %2;" : "=r"(d) : "f"(hi), "f"(lo));
    return d;
}
__device__ __forceinline__ float bf_round(float x) {
    return __bfloat162float(__float2bfloat16_rn(x));
}

// ---------------------------------------------------------------------------
// fp32 -> bf16 hi/lo splits (x; and all 4 weights in one launch)
// ---------------------------------------------------------------------------
__global__ __launch_bounds__(256)
void split_bf16(const float* __restrict__ in, __nv_bfloat16* __restrict__ hi,
                __nv_bfloat16* __restrict__ lo, int n4)
{
    int i = blockIdx.x * blockDim.x + threadIdx.x;
    if (i >= n4) return;
    float4 v = ((const float4*)in)[i];
    float f[4] = {v.x, v.y, v.z, v.w};
    unsigned short hs[4], ls[4];
    #pragma unroll
    for (int j = 0; j < 4; j++) {
        __nv_bfloat16 h = __float2bfloat16_rn(f[j]);
        float r = f[j] - __bfloat162float(h);
        __nv_bfloat16 l = __float2bfloat16_rn(r);
        hs[j] = __bfloat16_as_ushort(h);
        ls[j] = __bfloat16_as_ushort(l);
    }
    ((ushort4*)hi)[i] = make_ushort4(hs[0], hs[1], hs[2], hs[3]);
    ((ushort4*)lo)[i] = make_ushort4(ls[0], ls[1], ls[2], ls[3]);
}

__global__ __launch_bounds__(256)
void split_w4(const float* __restrict__ w0, const float* __restrict__ w1,
              const float* __restrict__ w2, const float* __restrict__ w3,
              __nv_bfloat16* __restrict__ hi, __nv_bfloat16* __restrict__ lo,
              int n4w)
{
    int i = blockIdx.x * blockDim.x + threadIdx.x;
    if (i >= 4 * n4w) return;
    const int m = i / n4w;
    const int j = i - m * n4w;
    const float* src = (m == 0) ? w0 : (m == 1) ? w1 : (m == 2) ? w2 : w3;
    float4 v = ((const float4*)src)[j];
    float f[4] = {v.x, v.y, v.z, v.w};
    unsigned short hs[4], ls[4];
    #pragma unroll
    for (int jj = 0; jj < 4; jj++) {
        __nv_bfloat16 h = __float2bfloat16_rn(f[jj]);
        float r = f[jj] - __bfloat162float(h);
        __nv_bfloat16 l = __float2bfloat16_rn(r);
        hs[jj] = __bfloat16_as_ushort(h);
        ls[jj] = __bfloat16_as_ushort(l);
    }
    ((ushort4*)hi)[i] = make_ushort4(hs[0], hs[1], hs[2], hs[3]);
    ((ushort4*)lo)[i] = make_ushort4(ls[0], ls[1], ls[2], ls[3]);
}

// ---------------------------------------------------------------------------
// bf16x3-split GEMM via mma.sync:  C = A B^T (NT), 128x256x32 CTA tile.
// 256 threads, 8 warps (2m x 4n), warp tile 64x64. 2-stage cp.async pipeline
// (known-good R8 configuration).
// ---------------------------------------------------------------------------
#define ATB     10240                 // 128 * 80
#define BTB     20480                 // 256 * 80
#define STG2    (2 * ATB + 2 * BTB)   // 61440
#define GSMEM2  (2 * STG2)            // 122880
#define KT      (KDIM / 32)           // 32

__global__ __launch_bounds__(256, 1)
void gemm_bf16x3(const __nv_bfloat16* __restrict__ Agh,
                 const __nv_bfloat16* __restrict__ Agl,
                 const __nv_bfloat16* __restrict__ Bgh,
                 const __nv_bfloat16* __restrict__ Bgl,
                 float* __restrict__ Cf,
                 __nv_bfloat16* __restrict__ Ch,
                 __nv_bfloat16* __restrict__ Cl,
                 float scale)
{
    extern __shared__ __align__(128) char smem_raw[];
    const uint32_t smem = smem_u32(smem_raw);

    const int tid    = threadIdx.x;
    const int lane   = tid & 31;
    const int wid    = tid >> 5;
    const int warp_m = wid & 1;
    const int warp_n = wid >> 1;
    const int row0   = blockIdx.y * 128;
    const int col0   = blockIdx.x * 256;

    const uint32_t aoff = (uint32_t)((lane & 15) * 80 + ((lane >> 4) << 4));
    const uint32_t boff = (uint32_t)((((lane >> 3) & 1) * 8 + (lane & 7)) * 80 +
                                     ((lane >> 4) << 4));

    float acc[4][8][4];
    #pragma unroll
    for (int mt = 0; mt < 4; mt++)
        #pragma unroll
        for (int nt = 0; nt < 8; nt++)
            #pragma unroll
            for (int q = 0; q < 4; q++) acc[mt][nt][q] = 0.f;

    const int r_lo = tid >> 2;
    const int k16  = tid & 3;

    #define LOAD_STAGE(sb, k0)                                                  \
    do {                                                                        \
        const size_t kofs = (size_t)(k0) + k16 * 8;                             \
        _Pragma("unroll")                                                       \
        for (int rr = 0; rr < 2; rr++) {                                        \
            const int r = r_lo + rr * 64;                                       \
            cp_async16((sb) + r * 80 + k16 * 16,                                \
                       Agh + (size_t)(row0 + r) * KDIM + kofs);                 \
            cp_async16((sb) + ATB + r * 80 + k16 * 16,                          \
                       Agl + (size_t)(row0 + r) * KDIM + kofs);                 \
        }                                                                       \
        _Pragma("unroll")                                                       \
        for (int rr = 0; rr < 4; rr++) {                                        \
            const int r = r_lo + rr * 64;                                       \
            cp_async16((sb) + 2 * ATB + r * 80 + k16 * 16,                      \
                       Bgh + (size_t)(col0 + r) * KDIM + kofs);                 \
            cp_async16((sb) + 2 * ATB + BTB + r * 80 + k16 * 16,                \
                       Bgl + (size_t)(col0 + r) * KDIM + kofs);                 \
        }                                                                       \
    } while (0)

    LOAD_STAGE(smem, 0);
    CP_COMMIT();

    for (int t = 0; t < KT; t++) {
        const int cur = t & 1;
        if (t + 1 < KT) {
            const uint32_t sb = smem + ((t + 1) & 1) * STG2;
            LOAD_STAGE(sb, (t + 1) * 32);
            CP_COMMIT();
            CP_WAIT(1);
        } else {
            CP_WAIT(0);
        }
        __syncthreads();

        const uint32_t sb  = smem + cur * STG2;
        const uint32_t Ahs = sb;
        const uint32_t Bhs = sb + 2 * ATB;

        #pragma unroll
        for (int kk = 0; kk < 2; kk++) {
            const uint32_t kkb = kk * 32;
            uint32_t ah[4][4];
            uint32_t al[4][4];
            uint32_t bh[4][4];
            uint32_t bl[4][4];
            #pragma unroll
            for (int mt = 0; mt < 4; mt++) {
                const uint32_t ad = Ahs + (warp_m * 64 + mt * 16) * 80 + kkb + aoff;
                LDSM4(ah[mt], ad);
                LDSM4(al[mt], ad + ATB);
            }
            #pragma unroll
            for (int p = 0; p < 4; p++) {
                const uint32_t bd = Bhs + (warp_n * 64 + p * 16) * 80 + kkb + boff;
                LDSM4(bh[p], bd);
                LDSM4(bl[p], bd + BTB);
            }
            #pragma unroll
            for (int mt = 0; mt < 4; mt++)
                #pragma unroll
                for (int nt = 0; nt < 8; nt++) {
                    float* d = acc[mt][nt];
                    const int p = nt >> 1;
                    const int q = nt & 1;
                    MMA16816(d, ah[mt], bh[p][q], bh[p][q + 2]);
                    MMA16816(d, ah[mt], bl[p][q], bl[p][q + 2]);
                    MMA16816(d, al[mt], bh[p][q], bh[p][q + 2]);
                }
        }
        __syncthreads();
    }
    #undef LOAD_STAGE

    // ---- epilogue ----
    const int rbase = row0 + warp_m * 64 + (lane >> 2);
    const int cbase = col0 + warp_n * 64 + (lane & 3) * 2;
    #pragma unroll
    for (int mt = 0; mt < 4; mt++) {
        #pragma unroll
        for (int nt = 0; nt < 8; nt++) {
            const int r = rbase + mt * 16;
            const int c = cbase + nt * 8;
            const float v0 = acc[mt][nt][0] * scale;
            const float v1 = acc[mt][nt][1] * scale;
            const float v2 = acc[mt][nt][2] * scale;
            const float v3 = acc[mt][nt][3] * scale;
            if (Cf) {
                *(float2*)&Cf[(size_t)r * NDIM + c]       = make_float2(v0, v1);
                *(float2*)&Cf[(size_t)(r + 8) * NDIM + c] = make_float2(v2, v3);
            }
            if (Ch) {
                const float h0 = bf_round(v0), h1 = bf_round(v1);
                const float h2 = bf_round(v2), h3 = bf_round(v3);
                *(uint32_t*)&Ch[(size_t)r * NDIM + c]       = bf2x(v1, v0);
                *(uint32_t*)&Cl[(size_t)r * NDIM + c]       = bf2x(v1 - h1, v0 - h0);
                *(uint32_t*)&Ch[(size_t)(r + 8) * NDIM + c] = bf2x(v3, v2);
                *(uint32_t*)&Cl[(size_t)(r + 8) * NDIM + c] = bf2x(v3 - h3, v2 - h2);
            }
        }
    }
}

// ---------------------------------------------------------------------------
// Tensor-core causal flash attention, bf16x3 split.
// 128 threads (4 warps), 64-row q-tile, __launch_bounds__(128,2) so TWO
// independent CTAs share each SM (barriers/softmax in one overlap MMAs in
// the other). Chunk c lives in smem stage (c+1)&1; chunk 0 prefetches
// during the Q load. Warp-uniform causal skip on the diagonal chunk.
// ---------------------------------------------------------------------------
#define APITCH  144
#define KV_TILE (64 * APITCH)
#define ASTAGE  (4 * KV_TILE)
#define ASMEM   (2 * ASTAGE)        // 73728

__global__ __launch_bounds__(128, 2)
void attn_mma(const __nv_bfloat16* __restrict__ Qh_, const __nv_bfloat16* __restrict__ Ql_,
              const __nv_bfloat16* __restrict__ Kh_, const __nv_bfloat16* __restrict__ Kl_,
              const __nv_bfloat16* __restrict__ Vh_, const __nv_bfloat16* __restrict__ Vl_,
              __nv_bfloat16* __restrict__ AOh, __nv_bfloat16* __restrict__ AOl)
{
    extern __shared__ __align__(128) char smx[];
    const uint32_t smem = smem_u32(smx);
    const int tid  = threadIdx.x;
    const int lane = tid & 31;
    const int w    = tid >> 5;                 // 0..3
    const int qt   = (NQT64 - 1) - blockIdx.x; // heavy tiles first
    const int h    = blockIdx.y;
    const int b    = blockIdx.z;
    const int q0   = qt * 64;
    const int hbase = h * 64;

    const uint32_t aoff = (uint32_t)((lane & 15) * APITCH + ((lane >> 4) << 4));
    const uint32_t boff = (uint32_t)((((lane >> 3) & 1) * 8 + (lane & 7)) * APITCH +
                                     ((lane >> 4) << 4));
    const uint32_t voff = aoff;

    const __nv_bfloat16* kvsrc[4];
    kvsrc[0] = Kh_; kvsrc[1] = Kl_; kvsrc[2] = Vh_; kvsrc[3] = Vl_;

    const int nch = qt + 1;

    // ---- prologue: Q (stage 0) and chunk 0 (stage 1) in flight together ----
    {
        const int r  = tid >> 1;               // 0..63
        const int c4 = (tid & 1) * 4;
        const size_t gq = ((size_t)(b * S_LEN + q0 + r)) * D_MODEL + hbase;
        const uint32_t d0 = smem + r * APITCH;
        #pragma unroll
        for (int j = 0; j < 4; j++) {
            cp_async16(d0 + (c4 + j) * 16, Qh_ + gq + (c4 + j) * 8);
            cp_async16(d0 + 2 * KV_TILE + (c4 + j) * 16, Ql_ + gq + (c4 + j) * 8);
        }
        CP_COMMIT();
    }
    {
        const uint32_t sb = smem + ASTAGE;     // chunk 0 -> stage 1
        #pragma unroll
        for (int i = 0; i < 16; i++) {
            const int tile = i >> 2;
            const int r    = ((i & 3) << 4) + (tid >> 3);
            const __nv_bfloat16* gp =
                kvsrc[tile] + ((size_t)(b * S_LEN + r)) * D_MODEL + hbase + (tid & 7) * 8;
            cp_async16(sb + tile * KV_TILE + r * APITCH + (tid & 7) * 16, gp);
        }
        CP_COMMIT();
    }
    CP_WAIT(1);
    __syncthreads();

    uint32_t qh[4][4], ql[4][4];
    {
        const uint32_t qtb = smem + (w * 16) * APITCH;
        #pragma unroll
        for (int ks = 0; ks < 4; ks++) {
            LDSM4(qh[ks], qtb + ks * 32 + aoff);
            LDSM4(ql[ks], qtb + 2 * KV_TILE + ks * 32 + aoff);
        }
    }
    __syncthreads();   // Q consumed; stage 0 free

    float o[8][4];
    #pragma unroll
    for (int nt = 0; nt < 8; nt++)
        #pragma unroll
        for (int e = 0; e < 4; e++) o[nt][e] = 0.f;
    float mi0 = -1e30f, mi1 = -1e30f, li0 = 0.f, li1 = 0.f;

    const int qmaxw = q0 + w * 16 + 15;

    for (int c = 0; c < nch; c++) {
        if (c + 1 < nch) {
            const uint32_t sb = smem + (c & 1) * ASTAGE;
            const int k0 = (c + 1) * 64;
            #pragma unroll
            for (int i = 0; i < 16; i++) {
                const int tile = i >> 2;
                const int r    = ((i & 3) << 4) + (tid >> 3);
                const __nv_bfloat16* gp =
                    kvsrc[tile] + ((size_t)(b * S_LEN + k0 + r)) * D_MODEL + hbase + (tid & 7) * 8;
                cp_async16(sb + tile * KV_TILE + r * APITCH + (tid & 7) * 16, gp);
            }
            CP_COMMIT();
            CP_WAIT(1);
        } else {
            CP_WAIT(0);
        }
        __syncthreads();

        const int c0 = c * 64;
        const bool diag = (c0 >= q0);
        const uint32_t sb  = smem + ((c + 1) & 1) * ASTAGE;
        const uint32_t Khs = sb;
        const uint32_t Kls = sb + KV_TILE;
        const uint32_t Vhs = sb + 2 * KV_TILE;
        const uint32_t Vls = sb + 3 * KV_TILE;

        float s[8][4];
        #pragma unroll
        for (int nt = 0; nt < 8; nt++)
            #pragma unroll
            for (int e = 0; e < 4; e++) s[nt][e] = 0.f;

        #pragma unroll
        for (int ks = 0; ks < 4; ks++) {
            uint32_t kh[4][4], kl[4][4];
            #pragma unroll
            for (int p = 0; p < 4; p++) {
                if (!diag || c0 + 16 * p <= qmaxw) {
                    LDSM4(kh[p], Khs + p * 16 * APITCH + ks * 32 + boff);
                    LDSM4(kl[p], Kls + p * 16 * APITCH + ks * 32 + boff);
                }
            }
            #pragma unroll
            for (int nt = 0; nt < 8; nt++) {
                if (!diag || c0 + 8 * nt <= qmaxw) {
                    const int p = nt >> 1;
                    const int q = nt & 1;
                    MMA16816(s[nt], qh[ks], kh[p][q], kh[p][q + 2]);
                    MMA16816(s[nt], ql[ks], kh[p][q], kh[p][q + 2]);
                    MMA16816(s[nt], qh[ks], kl[p][q], kl[p][q + 2]);
                }
            }
        }

        if (diag) {
            const int qr0 = q0 + w * 16 + (lane >> 2);
            #pragma unroll
            for (int nt = 0; nt < 8; nt++)
                #pragma unroll
                for (int e = 0; e < 4; e++) {
                    const int key = c0 + nt * 8 + 2 * (lane & 3) + (e & 1);
                    const int qr  = qr0 + (e >> 1) * 8;
                    if (key > qr) s[nt][e] = -1e30f;
                }
        }

        float rmax0 = -1e30f, rmax1 = -1e30f;
        #pragma unroll
        for (int nt = 0; nt < 8; nt++) {
            rmax0 = fmaxf(rmax0, fmaxf(s[nt][0], s[nt][1]));
            rmax1 = fmaxf(rmax1, fmaxf(s[nt][2], s[nt][3]));
        }
        rmax0 = fmaxf(rmax0, __shfl_xor_sync(0xffffffffu, rmax0, 1));
        rmax0 = fmaxf(rmax0, __shfl_xor_sync(0xffffffffu, rmax0, 2));
        rmax1 = fmaxf(rmax1, __shfl_xor_sync(0xffffffffu, rmax1, 1));
        rmax1 = fmaxf(rmax1, __shfl_xor_sync(0xffffffffu, rmax1, 2));

        const float mnew0 = fmaxf(mi0, rmax0);
        const float mnew1 = fmaxf(mi1, rmax1);
        const float alpha0 = __expf(mi0 - mnew0);
        const float alpha1 = __expf(mi1 - mnew1);
        mi0 = mnew0; mi1 = mnew1;

        float rsum0 = 0.f, rsum1 = 0.f;
        #pragma unroll
        for (int nt = 0; nt < 8; nt++) {
            s[nt][0] = __expf(s[nt][0] - mnew0);
            s[nt][1] = __expf(s[nt][1] - mnew0);
            s[nt][2] = __expf(s[nt][2] - mnew1);
            s[nt][3] = __expf(s[nt][3] - mnew1);
            rsum0 += s[nt][0] + s[nt][1];
            rsum1 += s[nt][2] + s[nt][3];
        }
        rsum0 += __shfl_xor_sync(0xffffffffu, rsum0, 1);
        rsum0 += __shfl_xor_sync(0xffffffffu, rsum0, 2);
        rsum1 += __shfl_xor_sync(0xffffffffu, rsum1, 1);
        rsum1 += __shfl_xor_sync(0xffffffffu, rsum1, 2);
        li0 = li0 * alpha0 + rsum0;
        li1 = li1 * alpha1 + rsum1;

        #pragma unroll
        for (int nt = 0; nt < 8; nt++) {
            o[nt][0] *= alpha0; o[nt][1] *= alpha0;
            o[nt][2] *= alpha1; o[nt][3] *= alpha1;
        }

        #pragma unroll
        for (int kb = 0; kb < 4; kb++) {
            if (!diag || c0 + 16 * kb <= qmaxw) {
                uint32_t ph[4], pl[4];
                {
                    const float* s0 = s[2 * kb];
                    const float* s1 = s[2 * kb + 1];
                    float h00 = bf_round(s0[0]), h01 = bf_round(s0[1]);
                    float h02 = bf_round(s0[2]), h03 = bf_round(s0[3]);
                    float h10 = bf_round(s1[0]), h11 = bf_round(s1[1]);
                    float h12 = bf_round(s1[2]), h13 = bf_round(s1[3]);
                    ph[0] = bf2x(s0[1], s0[0]);
                    ph[1] = bf2x(s0[3], s0[2]);
                    ph[2] = bf2x(s1[1], s1[0]);
                    ph[3] = bf2x(s1[3], s1[2]);
                    pl[0] = bf2x(s0[1] - h01, s0[0] - h00);
                    pl[1] = bf2x(s0[3] - h03, s0[2] - h02);
                    pl[2] = bf2x(s1[1] - h11, s1[0] - h10);
                    pl[3] = bf2x(s1[3] - h13, s1[2] - h12);
                }
                #pragma unroll
                for (int dt = 0; dt < 4; dt++) {
                    uint32_t vh[4], vl[4];
                    LDSM4T(vh, Vhs + kb * 16 * APITCH + dt * 32 + voff);
                    LDSM4T(vl, Vls + kb * 16 * APITCH + dt * 32 + voff);
                    #pragma unroll
                    for (int q = 0; q < 2; q++) {
                        const int nt = dt * 2 + q;
                        MMA16816(o[nt], ph, vh[2 * q], vh[2 * q + 1]);
                        MMA16816(o[nt], pl, vh[2 * q], vh[2 * q + 1]);
                        MMA16816(o[nt], ph, vl[2 * q], vl[2 * q + 1]);
                    }
                }
            }
        }
        __syncthreads();
    }

    // ---- epilogue: normalize, fused bf16 hi/lo split store ----
    const float inv0 = 1.f / li0;
    const float inv1 = 1.f / li1;
    const int qr0 = q0 + w * 16 + (lane >> 2);
    const int cb  = hbase + 2 * (lane & 3);
    #pragma unroll
    for (int nt = 0; nt < 8; nt++) {
        const float a0 = o[nt][0] * inv0, a1 = o[nt][1] * inv0;
        const float a2 = o[nt][2] * inv1, a3 = o[nt][3] * inv1;
        const float h0 = bf_round(a0), h1 = bf_round(a1);
        const float h2 = bf_round(a2), h3 = bf_round(a3);
        const size_t i0 = ((size_t)(b * S_LEN + qr0)) * D_MODEL + cb + nt * 8;
        const size_t i1 = ((size_t)(b * S_LEN + qr0 + 8)) * D_MODEL + cb + nt * 8;
        *(uint32_t*)&AOh[i0] = bf2x(a1, a0);
        *(uint32_t*)&AOl[i0] = bf2x(a1 - h1, a0 - h0);
        *(uint32_t*)&AOh[i1] = bf2x(a3, a2);
        *(uint32_t*)&AOl[i1] = bf2x(a3 - h3, a2 - h2);
    }
}

// ---------------------------------------------------------------------------
// Launch
// ---------------------------------------------------------------------------
extern "C" void kernel_launch(void* const* d_in, const int* in_sizes, int n_in,
                              void* d_out, int out_size)
{
    const float* x  = (const float*)d_in[0];
    float* out = (float*)d_out;

    __nv_bfloat16 *pxh, *pxl, *pwh, *pwl;
    __nv_bfloat16 *pqh, *pql, *pkh, *pkl, *pvh, *pvl, *paoh, *paol;
    cudaGetSymbolAddress((void**)&pxh,  g_xh);
    cudaGetSymbolAddress((void**)&pxl,  g_xl);
    cudaGetSymbolAddress((void**)&pwh,  g_wh);
    cudaGetSymbolAddress((void**)&pwl,  g_wl);
    cudaGetSymbolAddress((void**)&pqh,  g_qh);
    cudaGetSymbolAddress((void**)&pql,  g_ql);
    cudaGetSymbolAddress((void**)&pkh,  g_kh);
    cudaGetSymbolAddress((void**)&pkl,  g_kl);
    cudaGetSymbolAddress((void**)&pvh,  g_vh);
    cudaGetSymbolAddress((void**)&pvl,  g_vl);
    cudaGetSymbolAddress((void**)&paoh, g_aoh);
    cudaGetSymbolAddress((void**)&paol, g_aol);

    cudaFuncSetAttribute(gemm_bf16x3,
                         cudaFuncAttributeMaxDynamicSharedMemorySize, GSMEM2);
    cudaFuncSetAttribute(attn_mma,
                         cudaFuncAttributeMaxDynamicSharedMemorySize, ASMEM);

    const int n4e = MROWS * KDIM / 4;
    const int n4w = KDIM * NDIM / 4;

    // 1) split external inputs (x; all 4 weights in one launch)
    split_bf16<<<(n4e + 255) / 256, 256>>>(x, pxh, pxl, n4e);
    split_w4<<<(4 * n4w + 255) / 256, 256>>>(
        (const float*)d_in[1], (const float*)d_in[2],
        (const float*)d_in[3], (const float*)d_in[4],
        pwh, pwl, n4w);

    // 2) Q/K/V projections with fused hi/lo split epilogue (Q scaled 1/8)
    dim3 ggrid(NDIM / 256, MROWS / 128);   // (4, 32)
    gemm_bf16x3<<<ggrid, 256, GSMEM2>>>(pxh, pxl,
        pwh + 0 * (size_t)KDIM * NDIM, pwl + 0 * (size_t)KDIM * NDIM,
        (float*)nullptr, pqh, pql, 0.125f);
    gemm_bf16x3<<<ggrid, 256, GSMEM2>>>(pxh, pxl,
        pwh + 1 * (size_t)KDIM * NDIM, pwl + 1 * (size_t)KDIM * NDIM,
        (float*)nullptr, pkh, pkl, 1.f);
    gemm_bf16x3<<<ggrid, 256, GSMEM2>>>(pxh, pxl,
        pwh + 2 * (size_t)KDIM * NDIM, pwl + 2 * (size_t)KDIM * NDIM,
        (float*)nullptr, pvh, pvl, 1.f);

    // 3) tensor-core causal attention (2 CTAs/SM)
    dim3 agrid(NQT64, NHEAD, B_SZ);        // (32, 16, 2)
    attn_mma<<<agrid, 128, ASMEM>>>(pqh, pql, pkh, pkl, pvh, pvl, paoh, paol);

    // 4) output projection -> fp32 out
    gemm_bf16x3<<<ggrid, 256, GSMEM2>>>(paoh, paol,
        pwh + 3 * (size_t)KDIM * NDIM, pwl + 3 * (size_t)KDIM * NDIM,
        out, (__nv_bfloat16*)nullptr, (__nv_bfloat16*)nullptr, 1.f);
}

// round 13
// speedup vs baseline: 1.0502x; 1.0463x over previous
#include <cuda_runtime.h>
#include <cuda_bf16.h>
#include <cstdint>
#include <math.h>

// ---------------------------------------------------------------------------
// Problem constants
// ---------------------------------------------------------------------------
#define B_SZ    2
#define S_LEN   2048
#define D_MODEL 1024
#define NHEAD   16
#define DKH     64
#define MROWS   4096
#define KDIM    1024
#define NDIM    1024
#define NQT     (S_LEN / 128)     // 16 q-tiles of 128 rows

// ---------------------------------------------------------------------------
// Scratch (device globals)
// ---------------------------------------------------------------------------
__device__ __align__(16) __nv_bfloat16 g_xh [MROWS * KDIM];
__device__ __align__(16) __nv_bfloat16 g_xl [MROWS * KDIM];
__device__ __align__(16) __nv_bfloat16 g_wh [4 * KDIM * NDIM];
__device__ __align__(16) __nv_bfloat16 g_wl [4 * KDIM * NDIM];
__device__ __align__(16) __nv_bfloat16 g_qh [MROWS * D_MODEL];
__device__ __align__(16) __nv_bfloat16 g_ql [MROWS * D_MODEL];
__device__ __align__(16) __nv_bfloat16 g_kh [MROWS * D_MODEL];
__device__ __align__(16) __nv_bfloat16 g_kl [MROWS * D_MODEL];
__device__ __align__(16) __nv_bfloat16 g_vh [MROWS * D_MODEL];
__device__ __align__(16) __nv_bfloat16 g_vl [MROWS * D_MODEL];
__device__ __align__(16) __nv_bfloat16 g_aoh[MROWS * D_MODEL];
__device__ __align__(16) __nv_bfloat16 g_aol[MROWS * D_MODEL];

// ---------------------------------------------------------------------------
// PTX helpers (sm_80-era, valid at compute_100)
// ---------------------------------------------------------------------------
__device__ __forceinline__ uint32_t smem_u32(const void* p) {
    uint32_t a;
    asm("{ .reg .u64 t; cvta.to.shared.u64 t, %1; cvt.u32.u64 %0, t; }"
        : "=r"(a) : "l"(p));
    return a;
}

__device__ __forceinline__ void cp_async16(uint32_t dst, const void* src) {
    asm volatile("cp.async.cg.shared.global [%0], [%1], 16;"
                 :: "r"(dst), "l"(src) : "memory");
}
#define CP_COMMIT() asm volatile("cp.async.commit_group;" ::: "memory")
#define CP_WAIT(n)  asm volatile("cp.async.wait_group %0;" :: "n"(n) : "memory")

#define LDSM4(r, addr) \
    asm volatile("ldmatrix.sync.aligned.m8n8.x4.shared.b16 {%0,%1,%2,%3}, [%4];" \
                 : "=r"((r)[0]), "=r"((r)[1]), "=r"((r)[2]), "=r"((r)[3]) : "r"(addr))

#define LDSM4T(r, addr) \
    asm volatile("ldmatrix.sync.aligned.m8n8.x4.trans.shared.b16 {%0,%1,%2,%3}, [%4];" \
                 : "=r"((r)[0]), "=r"((r)[1]), "=r"((r)[2]), "=r"((r)[3]) : "r"(addr))

#define MMA16816(d, a, b0v, b1v) \
    asm volatile("mma.sync.aligned.m16n8k16.row.col.f32.bf16.bf16.f32 " \
                 "{%0,%1,%2,%3}, {%4,%5,%6,%7}, {%8,%9}, {%0,%1,%2,%3};" \
                 : "+f"((d)[0]), "+f"((d)[1]), "+f"((d)[2]), "+f"((d)[3]) \
                 : "r"((a)[0]), "r"((a)[1]), "r"((a)[2]), "r"((a)[3]), \
                   "r"(b0v), "r"(b1v))

__device__ __forceinline__ uint32_t bf2x(float hi, float lo) {
    uint32_t d;
    asm("cvt.rn.bf16x2.f32 %0, %1, %2;" : "=r"(d) : "f"(hi), "f"(lo));
    return d;
}
__device__ __forceinline__ float bf_round(float x) {
    return __bfloat162float(__float2bfloat16_rn(x));
}

// ---------------------------------------------------------------------------
// fp32 -> bf16 hi/lo splits (x; and all 4 weights in one launch)
// ---------------------------------------------------------------------------
__global__ __launch_bounds__(256)
void split_bf16(const float* __restrict__ in, __nv_bfloat16* __restrict__ hi,
                __nv_bfloat16* __restrict__ lo, int n4)
{
    int i = blockIdx.x * blockDim.x + threadIdx.x;
    if (i >= n4) return;
    float4 v = ((const float4*)in)[i];
    float f[4] = {v.x, v.y, v.z, v.w};
    unsigned short hs[4], ls[4];
    #pragma unroll
    for (int j = 0; j < 4; j++) {
        __nv_bfloat16 h = __float2bfloat16_rn(f[j]);
        float r = f[j] - __bfloat162float(h);
        __nv_bfloat16 l = __float2bfloat16_rn(r);
        hs[j] = __bfloat16_as_ushort(h);
        ls[j] = __bfloat16_as_ushort(l);
    }
    ((ushort4*)hi)[i] = make_ushort4(hs[0], hs[1], hs[2], hs[3]);
    ((ushort4*)lo)[i] = make_ushort4(ls[0], ls[1], ls[2], ls[3]);
}

__global__ __launch_bounds__(256)
void split_w4(const float* __restrict__ w0, const float* __restrict__ w1,
              const float* __restrict__ w2, const float* __restrict__ w3,
              __nv_bfloat16* __restrict__ hi, __nv_bfloat16* __restrict__ lo,
              int n4w)
{
    int i = blockIdx.x * blockDim.x + threadIdx.x;
    if (i >= 4 * n4w) return;
    const int m = i / n4w;
    const int j = i - m * n4w;
    const float* src = (m == 0) ? w0 : (m == 1) ? w1 : (m == 2) ? w2 : w3;
    float4 v = ((const float4*)src)[j];
    float f[4] = {v.x, v.y, v.z, v.w};
    unsigned short hs[4], ls[4];
    #pragma unroll
    for (int jj = 0; jj < 4; jj++) {
        __nv_bfloat16 h = __float2bfloat16_rn(f[jj]);
        float r = f[jj] - __bfloat162float(h);
        __nv_bfloat16 l = __float2bfloat16_rn(r);
        hs[jj] = __bfloat16_as_ushort(h);
        ls[jj] = __bfloat16_as_ushort(l);
    }
    ((ushort4*)hi)[i] = make_ushort4(hs[0], hs[1], hs[2], hs[3]);
    ((ushort4*)lo)[i] = make_ushort4(ls[0], ls[1], ls[2], ls[3]);
}

// ---------------------------------------------------------------------------
// bf16x3-split GEMM via mma.sync:  C = A B^T (NT), 128x256x64 CTA tile.
// 256 threads, 8 warps (2m x 4n), warp tile 64x64. BK=64 per stage (pitch
// 144B -> conflict-free ldmatrix), 2-stage cp.async pipeline. Halves the
// barrier count vs BK=32 and gives 4 K16 fragment batches per barrier.
// smem: stage = Ah(18432) Al(18432) Bh(36864) Bl(36864) = 110592, x2 stages.
// ---------------------------------------------------------------------------
#define GP      144                   // smem row pitch (128B data + 16B pad)
#define ATB     (128 * GP)            // 18432
#define BTB     (256 * GP)            // 36864
#define STG     (2 * ATB + 2 * BTB)   // 110592
#define GSMEM   (2 * STG)             // 221184
#define KT      (KDIM / 64)           // 16

__global__ __launch_bounds__(256, 1)
void gemm_bf16x3(const __nv_bfloat16* __restrict__ Agh,
                 const __nv_bfloat16* __restrict__ Agl,
                 const __nv_bfloat16* __restrict__ Bgh,
                 const __nv_bfloat16* __restrict__ Bgl,
                 float* __restrict__ Cf,
                 __nv_bfloat16* __restrict__ Ch,
                 __nv_bfloat16* __restrict__ Cl,
                 float scale)
{
    extern __shared__ __align__(128) char smem_raw[];
    const uint32_t smem = smem_u32(smem_raw);

    const int tid    = threadIdx.x;
    const int lane   = tid & 31;
    const int wid    = tid >> 5;
    const int warp_m = wid & 1;
    const int warp_n = wid >> 1;
    const int row0   = blockIdx.y * 128;
    const int col0   = blockIdx.x * 256;

    const uint32_t aoff = (uint32_t)((lane & 15) * GP + ((lane >> 4) << 4));
    const uint32_t boff = (uint32_t)((((lane >> 3) & 1) * 8 + (lane & 7)) * GP +
                                     ((lane >> 4) << 4));

    float acc[4][8][4];
    #pragma unroll
    for (int mt = 0; mt < 4; mt++)
        #pragma unroll
        for (int nt = 0; nt < 8; nt++)
            #pragma unroll
            for (int q = 0; q < 4; q++) acc[mt][nt][q] = 0.f;

    const int rt  = tid >> 3;           // 0..31 row within 32-row group
    const int ch8 = tid & 7;            // 16B chunk within 128B row payload

    // 24 x cp.async(16B)/thread per stage (A 4x32-row groups x hi/lo = 8;
    // B 8x32-row groups x hi/lo = 16)
    #define LOAD_STAGE(sb, k0)                                                  \
    do {                                                                        \
        const size_t kofs = (size_t)(k0) + ch8 * 8;                             \
        _Pragma("unroll")                                                       \
        for (int rr = 0; rr < 4; rr++) {                                        \
            const int r = rr * 32 + rt;                                         \
            cp_async16((sb) + r * GP + ch8 * 16,                                \
                       Agh + (size_t)(row0 + r) * KDIM + kofs);                 \
            cp_async16((sb) + ATB + r * GP + ch8 * 16,                          \
                       Agl + (size_t)(row0 + r) * KDIM + kofs);                 \
        }                                                                       \
        _Pragma("unroll")                                                       \
        for (int rr = 0; rr < 8; rr++) {                                        \
            const int r = rr * 32 + rt;                                         \
            cp_async16((sb) + 2 * ATB + r * GP + ch8 * 16,                      \
                       Bgh + (size_t)(col0 + r) * KDIM + kofs);                 \
            cp_async16((sb) + 2 * ATB + BTB + r * GP + ch8 * 16,                \
                       Bgl + (size_t)(col0 + r) * KDIM + kofs);                 \
        }                                                                       \
    } while (0)

    LOAD_STAGE(smem, 0);
    CP_COMMIT();

    for (int t = 0; t < KT; t++) {
        const int cur = t & 1;
        if (t + 1 < KT) {
            const uint32_t sb = smem + ((t + 1) & 1) * STG;
            LOAD_STAGE(sb, (t + 1) * 64);
            CP_COMMIT();
            CP_WAIT(1);
        } else {
            CP_WAIT(0);
        }
        __syncthreads();

        const uint32_t sb  = smem + cur * STG;
        const uint32_t Ahs = sb;
        const uint32_t Bhs = sb + 2 * ATB;

        #pragma unroll
        for (int kk = 0; kk < 4; kk++) {           // four K16 steps per stage
            const uint32_t kkb = kk * 32;
            uint32_t ah[4][4];
            uint32_t al[4][4];
            uint32_t bh[4][4];
            uint32_t bl[4][4];
            #pragma unroll
            for (int mt = 0; mt < 4; mt++) {
                const uint32_t ad = Ahs + (warp_m * 64 + mt * 16) * GP + kkb + aoff;
                LDSM4(ah[mt], ad);
                LDSM4(al[mt], ad + ATB);
            }
            #pragma unroll
            for (int p = 0; p < 4; p++) {
                const uint32_t bd = Bhs + (warp_n * 64 + p * 16) * GP + kkb + boff;
                LDSM4(bh[p], bd);
                LDSM4(bl[p], bd + BTB);
            }
            #pragma unroll
            for (int mt = 0; mt < 4; mt++)
                #pragma unroll
                for (int nt = 0; nt < 8; nt++) {
                    float* d = acc[mt][nt];
                    const int p = nt >> 1;
                    const int q = nt & 1;
                    MMA16816(d, ah[mt], bh[p][q], bh[p][q + 2]);
                    MMA16816(d, ah[mt], bl[p][q], bl[p][q + 2]);
                    MMA16816(d, al[mt], bh[p][q], bh[p][q + 2]);
                }
        }
        __syncthreads();
    }
    #undef LOAD_STAGE

    // ---- epilogue ----
    const int rbase = row0 + warp_m * 64 + (lane >> 2);
    const int cbase = col0 + warp_n * 64 + (lane & 3) * 2;
    #pragma unroll
    for (int mt = 0; mt < 4; mt++) {
        #pragma unroll
        for (int nt = 0; nt < 8; nt++) {
            const int r = rbase + mt * 16;
            const int c = cbase + nt * 8;
            const float v0 = acc[mt][nt][0] * scale;
            const float v1 = acc[mt][nt][1] * scale;
            const float v2 = acc[mt][nt][2] * scale;
            const float v3 = acc[mt][nt][3] * scale;
            if (Cf) {
                *(float2*)&Cf[(size_t)r * NDIM + c]       = make_float2(v0, v1);
                *(float2*)&Cf[(size_t)(r + 8) * NDIM + c] = make_float2(v2, v3);
            }
            if (Ch) {
                const float h0 = bf_round(v0), h1 = bf_round(v1);
                const float h2 = bf_round(v2), h3 = bf_round(v3);
                *(uint32_t*)&Ch[(size_t)r * NDIM + c]       = bf2x(v1, v0);
                *(uint32_t*)&Cl[(size_t)r * NDIM + c]       = bf2x(v1 - h1, v0 - h0);
                *(uint32_t*)&Ch[(size_t)(r + 8) * NDIM + c] = bf2x(v3, v2);
                *(uint32_t*)&Cl[(size_t)(r + 8) * NDIM + c] = bf2x(v3 - h3, v2 - h2);
            }
        }
    }
}

// ---------------------------------------------------------------------------
// Tensor-core causal flash attention, bf16x3 split — R8 configuration
// (256 threads, 8 warps, 128-row q-tile; measured 274.6us).
// ---------------------------------------------------------------------------
#define APITCH  144
#define KV_TILE (64 * APITCH)
#define ASTAGE  (4 * KV_TILE)
#define ASMEM   (2 * ASTAGE)

__global__ __launch_bounds__(256, 1)
void attn_mma(const __nv_bfloat16* __restrict__ Qh_, const __nv_bfloat16* __restrict__ Ql_,
              const __nv_bfloat16* __restrict__ Kh_, const __nv_bfloat16* __restrict__ Kl_,
              const __nv_bfloat16* __restrict__ Vh_, const __nv_bfloat16* __restrict__ Vl_,
              __nv_bfloat16* __restrict__ AOh, __nv_bfloat16* __restrict__ AOl)
{
    extern __shared__ __align__(128) char smx[];
    const uint32_t smem = smem_u32(smx);
    const int tid  = threadIdx.x;
    const int lane = tid & 31;
    const int w    = tid >> 5;
    const int qt   = (NQT - 1) - blockIdx.x;
    const int h    = blockIdx.y;
    const int b    = blockIdx.z;
    const int q0   = qt * 128;
    const int hbase = h * 64;

    const uint32_t aoff = (uint32_t)((lane & 15) * APITCH + ((lane >> 4) << 4));
    const uint32_t boff = (uint32_t)((((lane >> 3) & 1) * 8 + (lane & 7)) * APITCH +
                                     ((lane >> 4) << 4));
    const uint32_t voff = aoff;

    const __nv_bfloat16* kvsrc[4];
    kvsrc[0] = Kh_; kvsrc[1] = Kl_; kvsrc[2] = Vh_; kvsrc[3] = Vl_;

    const int nch  = 2 * (qt + 1);
    const int r_lo = tid >> 3;
    const int ch8  = tid & 7;

    // ---- prologue: Q (stage 0) and chunk 0 (stage 1) in flight together ----
    {
        const int r  = tid >> 1;
        const int c4 = (tid & 1) * 4;
        const size_t gq = ((size_t)(b * S_LEN + q0 + r)) * D_MODEL + hbase;
        const uint32_t d0 = smem + ((r >= 64) ? KV_TILE : 0) + (r & 63) * APITCH;
        #pragma unroll
        for (int j = 0; j < 4; j++) {
            cp_async16(d0 + (c4 + j) * 16, Qh_ + gq + (c4 + j) * 8);
            cp_async16(d0 + 2 * KV_TILE + (c4 + j) * 16, Ql_ + gq + (c4 + j) * 8);
        }
        CP_COMMIT();
    }
    {
        const uint32_t sb = smem + ASTAGE;   // chunk 0 -> stage 1
        #pragma unroll
        for (int i = 0; i < 8; i++) {
            const int tile = i >> 1;
            const int r    = ((i & 1) << 5) + r_lo;
            const __nv_bfloat16* gp =
                kvsrc[tile] + ((size_t)(b * S_LEN + r)) * D_MODEL + hbase + ch8 * 8;
            cp_async16(sb + tile * KV_TILE + r * APITCH + ch8 * 16, gp);
        }
        CP_COMMIT();
    }
    CP_WAIT(1);
    __syncthreads();

    uint32_t qh[4][4], ql[4][4];
    {
        const uint32_t qtb = smem + ((w >= 4) ? KV_TILE : 0) + (w & 3) * 16 * APITCH;
        #pragma unroll
        for (int ks = 0; ks < 4; ks++) {
            LDSM4(qh[ks], qtb + ks * 32 + aoff);
            LDSM4(ql[ks], qtb + 2 * KV_TILE + ks * 32 + aoff);
        }
    }
    __syncthreads();   // Q consumed; stage 0 free

    float o[8][4];
    #pragma unroll
    for (int nt = 0; nt < 8; nt++)
        #pragma unroll
        for (int e = 0; e < 4; e++) o[nt][e] = 0.f;
    float mi0 = -1e30f, mi1 = -1e30f, li0 = 0.f, li1 = 0.f;

    const int qmaxw = q0 + w * 16 + 15;

    for (int c = 0; c < nch; c++) {
        if (c + 1 < nch) {
            const uint32_t sb = smem + (c & 1) * ASTAGE;   // chunk c+1 -> stage c&1
            const int k0 = (c + 1) * 64;
            #pragma unroll
            for (int i = 0; i < 8; i++) {
                const int tile = i >> 1;
                const int r    = ((i & 1) << 5) + r_lo;
                const __nv_bfloat16* gp =
                    kvsrc[tile] + ((size_t)(b * S_LEN + k0 + r)) * D_MODEL + hbase + ch8 * 8;
                cp_async16(sb + tile * KV_TILE + r * APITCH + ch8 * 16, gp);
            }
            CP_COMMIT();
            CP_WAIT(1);
        } else {
            CP_WAIT(0);
        }
        __syncthreads();

        const int c0 = c * 64;
        const bool diag = (c0 >= q0);
        const uint32_t sb  = smem + ((c + 1) & 1) * ASTAGE;
        const uint32_t Khs = sb;
        const uint32_t Kls = sb + KV_TILE;
        const uint32_t Vhs = sb + 2 * KV_TILE;
        const uint32_t Vls = sb + 3 * KV_TILE;

        float s[8][4];
        #pragma unroll
        for (int nt = 0; nt < 8; nt++)
            #pragma unroll
            for (int e = 0; e < 4; e++) s[nt][e] = 0.f;

        #pragma unroll
        for (int ks = 0; ks < 4; ks++) {
            uint32_t kh[4][4], kl[4][4];
            #pragma unroll
            for (int p = 0; p < 4; p++) {
                if (!diag || c0 + 16 * p <= qmaxw) {
                    LDSM4(kh[p], Khs + p * 16 * APITCH + ks * 32 + boff);
                    LDSM4(kl[p], Kls + p * 16 * APITCH + ks * 32 + boff);
                }
            }
            #pragma unroll
            for (int nt = 0; nt < 8; nt++) {
                if (!diag || c0 + 8 * nt <= qmaxw) {
                    const int p = nt >> 1;
                    const int q = nt & 1;
                    MMA16816(s[nt], qh[ks], kh[p][q], kh[p][q + 2]);
                    MMA16816(s[nt], ql[ks], kh[p][q], kh[p][q + 2]);
                    MMA16816(s[nt], qh[ks], kl[p][q], kl[p][q + 2]);
                }
            }
        }

        if (diag) {
            const int qr0 = q0 + w * 16 + (lane >> 2);
            #pragma unroll
            for (int nt = 0; nt < 8; nt++)
                #pragma unroll
                for (int e = 0; e < 4; e++) {
                    const int key = c0 + nt * 8 + 2 * (lane & 3) + (e & 1);
                    const int qr  = qr0 + (e >> 1) * 8;
                    if (key > qr) s[nt][e] = -1e30f;
                }
        }

        float rmax0 = -1e30f, rmax1 = -1e30f;
        #pragma unroll
        for (int nt = 0; nt < 8; nt++) {
            rmax0 = fmaxf(rmax0, fmaxf(s[nt][0], s[nt][1]));
            rmax1 = fmaxf(rmax1, fmaxf(s[nt][2], s[nt][3]));
        }
        rmax0 = fmaxf(rmax0, __shfl_xor_sync(0xffffffffu, rmax0, 1));
        rmax0 = fmaxf(rmax0, __shfl_xor_sync(0xffffffffu, rmax0, 2));
        rmax1 = fmaxf(rmax1, __shfl_xor_sync(0xffffffffu, rmax1, 1));
        rmax1 = fmaxf(rmax1, __shfl_xor_sync(0xffffffffu, rmax1, 2));

        const float mnew0 = fmaxf(mi0, rmax0);
        const float mnew1 = fmaxf(mi1, rmax1);
        const float alpha0 = __expf(mi0 - mnew0);
        const float alpha1 = __expf(mi1 - mnew1);
        mi0 = mnew0; mi1 = mnew1;

        float rsum0 = 0.f, rsum1 = 0.f;
        #pragma unroll
        for (int nt = 0; nt < 8; nt++) {
            s[nt][0] = __expf(s[nt][0] - mnew0);
            s[nt][1] = __expf(s[nt][1] - mnew0);
            s[nt][2] = __expf(s[nt][2] - mnew1);
            s[nt][3] = __expf(s[nt][3] - mnew1);
            rsum0 += s[nt][0] + s[nt][1];
            rsum1 += s[nt][2] + s[nt][3];
        }
        rsum0 += __shfl_xor_sync(0xffffffffu, rsum0, 1);
        rsum0 += __shfl_xor_sync(0xffffffffu, rsum0, 2);
        rsum1 += __shfl_xor_sync(0xffffffffu, rsum1, 1);
        rsum1 += __shfl_xor_sync(0xffffffffu, rsum1, 2);
        li0 = li0 * alpha0 + rsum0;
        li1 = li1 * alpha1 + rsum1;

        #pragma unroll
        for (int nt = 0; nt < 8; nt++) {
            o[nt][0] *= alpha0; o[nt][1] *= alpha0;
            o[nt][2] *= alpha1; o[nt][3] *= alpha1;
        }

        #pragma unroll
        for (int kb = 0; kb < 4; kb++) {
            if (!diag || c0 + 16 * kb <= qmaxw) {
                uint32_t ph[4], pl[4];
                {
                    const float* s0 = s[2 * kb];
                    const float* s1 = s[2 * kb + 1];
                    float h00 = bf_round(s0[0]), h01 = bf_round(s0[1]);
                    float h02 = bf_round(s0[2]), h03 = bf_round(s0[3]);
                    float h10 = bf_round(s1[0]), h11 = bf_round(s1[1]);
                    float h12 = bf_round(s1[2]), h13 = bf_round(s1[3]);
                    ph[0] = bf2x(s0[1], s0[0]);
                    ph[1] = bf2x(s0[3], s0[2]);
                    ph[2] = bf2x(s1[1], s1[0]);
                    ph[3] = bf2x(s1[3], s1[2]);
                    pl[0] = bf2x(s0[1] - h01, s0[0] - h00);
                    pl[1] = bf2x(s0[3] - h03, s0[2] - h02);
                    pl[2] = bf2x(s1[1] - h11, s1[0] - h10);
                    pl[3] = bf2x(s1[3] - h13, s1[2] - h12);
                }
                #pragma unroll
                for (int dt = 0; dt < 4; dt++) {
                    uint32_t vh[4], vl[4];
                    LDSM4T(vh, Vhs + kb * 16 * APITCH + dt * 32 + voff);
                    LDSM4T(vl, Vls + kb * 16 * APITCH + dt * 32 + voff);
                    #pragma unroll
                    for (int q = 0; q < 2; q++) {
                        const int nt = dt * 2 + q;
                        MMA16816(o[nt], ph, vh[2 * q], vh[2 * q + 1]);
                        MMA16816(o[nt], pl, vh[2 * q], vh[2 * q + 1]);
                        MMA16816(o[nt], ph, vl[2 * q], vl[2 * q + 1]);
                    }
                }
            }
        }
        __syncthreads();
    }

    // ---- epilogue: normalize, fused bf16 hi/lo split store ----
    const float inv0 = 1.f / li0;
    const float inv1 = 1.f / li1;
    const int qr0 = q0 + w * 16 + (lane >> 2);
    const int cb  = hbase + 2 * (lane & 3);
    #pragma unroll
    for (int nt = 0; nt < 8; nt++) {
        const float a0 = o[nt][0] * inv0, a1 = o[nt][1] * inv0;
        const float a2 = o[nt][2] * inv1, a3 = o[nt][3] * inv1;
        const float h0 = bf_round(a0), h1 = bf_round(a1);
        const float h2 = bf_round(a2), h3 = bf_round(a3);
        const size_t i0 = ((size_t)(b * S_LEN + qr0)) * D_MODEL + cb + nt * 8;
        const size_t i1 = ((size_t)(b * S_LEN + qr0 + 8)) * D_MODEL + cb + nt * 8;
        *(uint32_t*)&AOh[i0] = bf2x(a1, a0);
        *(uint32_t*)&AOl[i0] = bf2x(a1 - h1, a0 - h0);
        *(uint32_t*)&AOh[i1] = bf2x(a3, a2);
        *(uint32_t*)&AOl[i1] = bf2x(a3 - h3, a2 - h2);
    }
}

// ---------------------------------------------------------------------------
// Launch
// ---------------------------------------------------------------------------
extern "C" void kernel_launch(void* const* d_in, const int* in_sizes, int n_in,
                              void* d_out, int out_size)
{
    const float* x  = (const float*)d_in[0];
    float* out = (float*)d_out;

    __nv_bfloat16 *pxh, *pxl, *pwh, *pwl;
    __nv_bfloat16 *pqh, *pql, *pkh, *pkl, *pvh, *pvl, *paoh, *paol;
    cudaGetSymbolAddress((void**)&pxh,  g_xh);
    cudaGetSymbolAddress((void**)&pxl,  g_xl);
    cudaGetSymbolAddress((void**)&pwh,  g_wh);
    cudaGetSymbolAddress((void**)&pwl,  g_wl);
    cudaGetSymbolAddress((void**)&pqh,  g_qh);
    cudaGetSymbolAddress((void**)&pql,  g_ql);
    cudaGetSymbolAddress((void**)&pkh,  g_kh);
    cudaGetSymbolAddress((void**)&pkl,  g_kl);
    cudaGetSymbolAddress((void**)&pvh,  g_vh);
    cudaGetSymbolAddress((void**)&pvl,  g_vl);
    cudaGetSymbolAddress((void**)&paoh, g_aoh);
    cudaGetSymbolAddress((void**)&paol, g_aol);

    cudaFuncSetAttribute(gemm_bf16x3,
                         cudaFuncAttributeMaxDynamicSharedMemorySize, GSMEM);
    cudaFuncSetAttribute(attn_mma,
                         cudaFuncAttributeMaxDynamicSharedMemorySize, ASMEM);

    const int n4e = MROWS * KDIM / 4;
    const int n4w = KDIM * NDIM / 4;

    // 1) split external inputs (x; all 4 weights in one launch)
    split_bf16<<<(n4e + 255) / 256, 256>>>(x, pxh, pxl, n4e);
    split_w4<<<(4 * n4w + 255) / 256, 256>>>(
        (const float*)d_in[1], (const float*)d_in[2],
        (const float*)d_in[3], (const float*)d_in[4],
        pwh, pwl, n4w);

    // 2) Q/K/V projections with fused hi/lo split epilogue (Q scaled 1/8)
    dim3 ggrid(NDIM / 256, MROWS / 128);   // (4, 32)
    gemm_bf16x3<<<ggrid, 256, GSMEM>>>(pxh, pxl,
        pwh + 0 * (size_t)KDIM * NDIM, pwl + 0 * (size_t)KDIM * NDIM,
        (float*)nullptr, pqh, pql, 0.125f);
    gemm_bf16x3<<<ggrid, 256, GSMEM>>>(pxh, pxl,
        pwh + 1 * (size_t)KDIM * NDIM, pwl + 1 * (size_t)KDIM * NDIM,
        (float*)nullptr, pkh, pkl, 1.f);
    gemm_bf16x3<<<ggrid, 256, GSMEM>>>(pxh, pxl,
        pwh + 2 * (size_t)KDIM * NDIM, pwl + 2 * (size_t)KDIM * NDIM,
        (float*)nullptr, pvh, pvl, 1.f);

    // 3) tensor-core causal attention (R8 config)
    dim3 agrid(NQT, NHEAD, B_SZ);          // (16, 16, 2)
    attn_mma<<<agrid, 256, ASMEM>>>(pqh, pql, pkh, pkl, pvh, pvl, paoh, paol);

    // 4) output projection -> fp32 out
    gemm_bf16x3<<<ggrid, 256, GSMEM>>>(paoh, paol,
        pwh + 3 * (size_t)KDIM * NDIM, pwl + 3 * (size_t)KDIM * NDIM,
        out, (__nv_bfloat16*)nullptr, (__nv_bfloat16*)nullptr, 1.f);
}

// round 14
// speedup vs baseline: 1.2862x; 1.2247x over previous
#include <cuda_runtime.h>
#include <cuda_fp16.h>
#include <cstdint>
#include <math.h>

// ---------------------------------------------------------------------------
// Problem constants
// ---------------------------------------------------------------------------
#define B_SZ    2
#define S_LEN   2048
#define D_MODEL 1024
#define NHEAD   16
#define DKH     64
#define MROWS   4096
#define KDIM    1024
#define NDIM    1024
#define NQT     (S_LEN / 128)     // 16 q-tiles of 128 rows

// ---------------------------------------------------------------------------
// Scratch (device globals)
// ---------------------------------------------------------------------------
__device__ __align__(16) __half g_xh [MROWS * KDIM];
__device__ __align__(16) __half g_xl [MROWS * KDIM];
__device__ __align__(16) __half g_wh [4 * KDIM * NDIM];     // weights hi only
__device__ __align__(16) __half g_qh [MROWS * D_MODEL];
__device__ __align__(16) __half g_ql [MROWS * D_MODEL];
__device__ __align__(16) __half g_kh [MROWS * D_MODEL];
__device__ __align__(16) __half g_kl [MROWS * D_MODEL];
__device__ __align__(16) __half g_vh [MROWS * D_MODEL];
__device__ __align__(16) __half g_vl [MROWS * D_MODEL];
__device__ __align__(16) __half g_aoh[MROWS * D_MODEL];
__device__ __align__(16) __half g_aol[MROWS * D_MODEL];

// ---------------------------------------------------------------------------
// PTX helpers (sm_80-era, valid at compute_100)
// ---------------------------------------------------------------------------
__device__ __forceinline__ uint32_t smem_u32(const void* p) {
    uint32_t a;
    asm("{ .reg .u64 t; cvta.to.shared.u64 t, %1; cvt.u32.u64 %0, t; }"
        : "=r"(a) : "l"(p));
    return a;
}

__device__ __forceinline__ void cp_async16(uint32_t dst, const void* src) {
    asm volatile("cp.async.cg.shared.global [%0], [%1], 16;"
                 :: "r"(dst), "l"(src) : "memory");
}
#define CP_COMMIT() asm volatile("cp.async.commit_group;" ::: "memory")
#define CP_WAIT(n)  asm volatile("cp.async.wait_group %0;" :: "n"(n) : "memory")

#define LDSM4(r, addr) \
    asm volatile("ldmatrix.sync.aligned.m8n8.x4.shared.b16 {%0,%1,%2,%3}, [%4];" \
                 : "=r"((r)[0]), "=r"((r)[1]), "=r"((r)[2]), "=r"((r)[3]) : "r"(addr))

#define LDSM4T(r, addr) \
    asm volatile("ldmatrix.sync.aligned.m8n8.x4.trans.shared.b16 {%0,%1,%2,%3}, [%4];" \
                 : "=r"((r)[0]), "=r"((r)[1]), "=r"((r)[2]), "=r"((r)[3]) : "r"(addr))

#define MMA16816(d, a, b0v, b1v) \
    asm volatile("mma.sync.aligned.m16n8k16.row.col.f32.f16.f16.f32 " \
                 "{%0,%1,%2,%3}, {%4,%5,%6,%7}, {%8,%9}, {%0,%1,%2,%3};" \
                 : "+f"((d)[0]), "+f"((d)[1]), "+f"((d)[2]), "+f"((d)[3]) \
                 : "r"((a)[0]), "r"((a)[1]), "r"((a)[2]), "r"((a)[3]), \
                   "r"(b0v), "r"(b1v))

// pack two fp32 -> half2 (lo in low 16 bits)
__device__ __forceinline__ uint32_t h2x(float lo, float hi) {
    __half2 h = __floats2half2_rn(lo, hi);
    return *(uint32_t*)&h;
}
__device__ __forceinline__ float h_round(float x) {
    return __half2float(__float2half_rn(x));
}

// ---------------------------------------------------------------------------
// fp32 -> fp16 hi/lo split for x; fp32 -> fp16 (hi only) for the 4 weights
// ---------------------------------------------------------------------------
__global__ __launch_bounds__(256)
void split_f16(const float* __restrict__ in, __half* __restrict__ hi,
               __half* __restrict__ lo, int n4)
{
    int i = blockIdx.x * blockDim.x + threadIdx.x;
    if (i >= n4) return;
    float4 v = ((const float4*)in)[i];
    float f[4] = {v.x, v.y, v.z, v.w};
    unsigned short hs[4], ls[4];
    #pragma unroll
    for (int j = 0; j < 4; j++) {
        __half h = __float2half_rn(f[j]);
        float r = f[j] - __half2float(h);
        __half l = __float2half_rn(r);
        hs[j] = __half_as_ushort(h);
        ls[j] = __half_as_ushort(l);
    }
    ((ushort4*)hi)[i] = make_ushort4(hs[0], hs[1], hs[2], hs[3]);
    ((ushort4*)lo)[i] = make_ushort4(ls[0], ls[1], ls[2], ls[3]);
}

__global__ __launch_bounds__(256)
void convert_w4(const float* __restrict__ w0, const float* __restrict__ w1,
                const float* __restrict__ w2, const float* __restrict__ w3,
                __half* __restrict__ hi, int n4w)
{
    int i = blockIdx.x * blockDim.x + threadIdx.x;
    if (i >= 4 * n4w) return;
    const int m = i / n4w;
    const int j = i - m * n4w;
    const float* src = (m == 0) ? w0 : (m == 1) ? w1 : (m == 2) ? w2 : w3;
    float4 v = ((const float4*)src)[j];
    ushort4 o;
    o.x = __half_as_ushort(__float2half_rn(v.x));
    o.y = __half_as_ushort(__float2half_rn(v.y));
    o.z = __half_as_ushort(__float2half_rn(v.z));
    o.w = __half_as_ushort(__float2half_rn(v.w));
    ((ushort4*)hi)[i] = o;
}

// ---------------------------------------------------------------------------
// fp16x2-split GEMM via mma.sync:  C = (Ah+Al) Bh^T (NT), 128x256x64 tile.
// 256 threads, 8 warps (2m x 4n), warp tile 64x64. BK=64, 2-stage cp.async.
// 2 MMAs per (mt,nt) micro-tile: Ah*Bh + Al*Bh.  Error ~ A*Bl ~ 2^-12 RMS.
// smem stage: Ah(18432) Al(18432) Bh(36864) = 73728, x2 stages = 147456.
// ---------------------------------------------------------------------------
#define GP      144                   // smem row pitch (128B data + 16B pad)
#define ATB     (128 * GP)            // 18432
#define BTB     (256 * GP)            // 36864
#define STG     (2 * ATB + BTB)       // 73728
#define GSMEM   (2 * STG)             // 147456
#define KT      (KDIM / 64)           // 16

__global__ __launch_bounds__(256, 1)
void gemm_f16x2(const __half* __restrict__ Agh,
                const __half* __restrict__ Agl,
                const __half* __restrict__ Bgh,
                float* __restrict__ Cf,
                __half* __restrict__ Ch,
                __half* __restrict__ Cl,
                float scale)
{
    extern __shared__ __align__(128) char smem_raw[];
    const uint32_t smem = smem_u32(smem_raw);

    const int tid    = threadIdx.x;
    const int lane   = tid & 31;
    const int wid    = tid >> 5;
    const int warp_m = wid & 1;
    const int warp_n = wid >> 1;
    const int row0   = blockIdx.y * 128;
    const int col0   = blockIdx.x * 256;

    const uint32_t aoff = (uint32_t)((lane & 15) * GP + ((lane >> 4) << 4));
    const uint32_t boff = (uint32_t)((((lane >> 3) & 1) * 8 + (lane & 7)) * GP +
                                     ((lane >> 4) << 4));

    float acc[4][8][4];
    #pragma unroll
    for (int mt = 0; mt < 4; mt++)
        #pragma unroll
        for (int nt = 0; nt < 8; nt++)
            #pragma unroll
            for (int q = 0; q < 4; q++) acc[mt][nt][q] = 0.f;

    const int rt  = tid >> 3;           // 0..31 row within 32-row group
    const int ch8 = tid & 7;            // 16B chunk within 128B row payload

    // 16 x cp.async(16B)/thread per stage (A hi/lo 4+4; B hi 8)
    #define LOAD_STAGE(sb, k0)                                                  \
    do {                                                                        \
        const size_t kofs = (size_t)(k0) + ch8 * 8;                             \
        _Pragma("unroll")                                                       \
        for (int rr = 0; rr < 4; rr++) {                                        \
            const int r = rr * 32 + rt;                                         \
            cp_async16((sb) + r * GP + ch8 * 16,                                \
                       Agh + (size_t)(row0 + r) * KDIM + kofs);                 \
            cp_async16((sb) + ATB + r * GP + ch8 * 16,                          \
                       Agl + (size_t)(row0 + r) * KDIM + kofs);                 \
        }                                                                       \
        _Pragma("unroll")                                                       \
        for (int rr = 0; rr < 8; rr++) {                                        \
            const int r = rr * 32 + rt;                                         \
            cp_async16((sb) + 2 * ATB + r * GP + ch8 * 16,                      \
                       Bgh + (size_t)(col0 + r) * KDIM + kofs);                 \
        }                                                                       \
    } while (0)

    LOAD_STAGE(smem, 0);
    CP_COMMIT();

    for (int t = 0; t < KT; t++) {
        const int cur = t & 1;
        if (t + 1 < KT) {
            const uint32_t sb = smem + ((t + 1) & 1) * STG;
            LOAD_STAGE(sb, (t + 1) * 64);
            CP_COMMIT();
            CP_WAIT(1);
        } else {
            CP_WAIT(0);
        }
        __syncthreads();

        const uint32_t sb  = smem + cur * STG;
        const uint32_t Ahs = sb;
        const uint32_t Bhs = sb + 2 * ATB;

        #pragma unroll
        for (int kk = 0; kk < 4; kk++) {           // four K16 steps per stage
            const uint32_t kkb = kk * 32;
            uint32_t ah[4][4];
            uint32_t al[4][4];
            uint32_t bh[4][4];
            #pragma unroll
            for (int mt = 0; mt < 4; mt++) {
                const uint32_t ad = Ahs + (warp_m * 64 + mt * 16) * GP + kkb + aoff;
                LDSM4(ah[mt], ad);
                LDSM4(al[mt], ad + ATB);
            }
            #pragma unroll
            for (int p = 0; p < 4; p++) {
                const uint32_t bd = Bhs + (warp_n * 64 + p * 16) * GP + kkb + boff;
                LDSM4(bh[p], bd);
            }
            #pragma unroll
            for (int mt = 0; mt < 4; mt++)
                #pragma unroll
                for (int nt = 0; nt < 8; nt++) {
                    float* d = acc[mt][nt];
                    const int p = nt >> 1;
                    const int q = nt & 1;
                    MMA16816(d, ah[mt], bh[p][q], bh[p][q + 2]);
                    MMA16816(d, al[mt], bh[p][q], bh[p][q + 2]);
                }
        }
        __syncthreads();
    }
    #undef LOAD_STAGE

    // ---- epilogue: fp32 store and/or fused fp16 hi/lo split store ----
    const int rbase = row0 + warp_m * 64 + (lane >> 2);
    const int cbase = col0 + warp_n * 64 + (lane & 3) * 2;
    #pragma unroll
    for (int mt = 0; mt < 4; mt++) {
        #pragma unroll
        for (int nt = 0; nt < 8; nt++) {
            const int r = rbase + mt * 16;
            const int c = cbase + nt * 8;
            const float v0 = acc[mt][nt][0] * scale;
            const float v1 = acc[mt][nt][1] * scale;
            const float v2 = acc[mt][nt][2] * scale;
            const float v3 = acc[mt][nt][3] * scale;
            if (Cf) {
                *(float2*)&Cf[(size_t)r * NDIM + c]       = make_float2(v0, v1);
                *(float2*)&Cf[(size_t)(r + 8) * NDIM + c] = make_float2(v2, v3);
            }
            if (Ch) {
                const float h0 = h_round(v0), h1 = h_round(v1);
                const float h2 = h_round(v2), h3 = h_round(v3);
                *(uint32_t*)&Ch[(size_t)r * NDIM + c]       = h2x(v0, v1);
                *(uint32_t*)&Cl[(size_t)r * NDIM + c]       = h2x(v0 - h0, v1 - h1);
                *(uint32_t*)&Ch[(size_t)(r + 8) * NDIM + c] = h2x(v2, v3);
                *(uint32_t*)&Cl[(size_t)(r + 8) * NDIM + c] = h2x(v2 - h2, v3 - h3);
            }
        }
    }
}

// ---------------------------------------------------------------------------
// Tensor-core causal flash attention, fp16x3 split (same structure as the
// proven R8/R13 bf16 version; fp16 is strictly more accurate here).
// 256 threads, 8 warps, 128-row q-tile.
// ---------------------------------------------------------------------------
#define APITCH  144
#define KV_TILE (64 * APITCH)
#define ASTAGE  (4 * KV_TILE)
#define ASMEM   (2 * ASTAGE)

__global__ __launch_bounds__(256, 1)
void attn_mma(const __half* __restrict__ Qh_, const __half* __restrict__ Ql_,
              const __half* __restrict__ Kh_, const __half* __restrict__ Kl_,
              const __half* __restrict__ Vh_, const __half* __restrict__ Vl_,
              __half* __restrict__ AOh, __half* __restrict__ AOl)
{
    extern __shared__ __align__(128) char smx[];
    const uint32_t smem = smem_u32(smx);
    const int tid  = threadIdx.x;
    const int lane = tid & 31;
    const int w    = tid >> 5;
    const int qt   = (NQT - 1) - blockIdx.x;
    const int h    = blockIdx.y;
    const int b    = blockIdx.z;
    const int q0   = qt * 128;
    const int hbase = h * 64;

    const uint32_t aoff = (uint32_t)((lane & 15) * APITCH + ((lane >> 4) << 4));
    const uint32_t boff = (uint32_t)((((lane >> 3) & 1) * 8 + (lane & 7)) * APITCH +
                                     ((lane >> 4) << 4));
    const uint32_t voff = aoff;

    const __half* kvsrc[4];
    kvsrc[0] = Kh_; kvsrc[1] = Kl_; kvsrc[2] = Vh_; kvsrc[3] = Vl_;

    const int nch  = 2 * (qt + 1);
    const int r_lo = tid >> 3;
    const int ch8  = tid & 7;

    // ---- prologue: Q (stage 0) and chunk 0 (stage 1) in flight together ----
    {
        const int r  = tid >> 1;
        const int c4 = (tid & 1) * 4;
        const size_t gq = ((size_t)(b * S_LEN + q0 + r)) * D_MODEL + hbase;
        const uint32_t d0 = smem + ((r >= 64) ? KV_TILE : 0) + (r & 63) * APITCH;
        #pragma unroll
        for (int j = 0; j < 4; j++) {
            cp_async16(d0 + (c4 + j) * 16, Qh_ + gq + (c4 + j) * 8);
            cp_async16(d0 + 2 * KV_TILE + (c4 + j) * 16, Ql_ + gq + (c4 + j) * 8);
        }
        CP_COMMIT();
    }
    {
        const uint32_t sb = smem + ASTAGE;   // chunk 0 -> stage 1
        #pragma unroll
        for (int i = 0; i < 8; i++) {
            const int tile = i >> 1;
            const int r    = ((i & 1) << 5) + r_lo;
            const __half* gp =
                kvsrc[tile] + ((size_t)(b * S_LEN + r)) * D_MODEL + hbase + ch8 * 8;
            cp_async16(sb + tile * KV_TILE + r * APITCH + ch8 * 16, gp);
        }
        CP_COMMIT();
    }
    CP_WAIT(1);
    __syncthreads();

    uint32_t qh[4][4], ql[4][4];
    {
        const uint32_t qtb = smem + ((w >= 4) ? KV_TILE : 0) + (w & 3) * 16 * APITCH;
        #pragma unroll
        for (int ks = 0; ks < 4; ks++) {
            LDSM4(qh[ks], qtb + ks * 32 + aoff);
            LDSM4(ql[ks], qtb + 2 * KV_TILE + ks * 32 + aoff);
        }
    }
    __syncthreads();   // Q consumed; stage 0 free

    float o[8][4];
    #pragma unroll
    for (int nt = 0; nt < 8; nt++)
        #pragma unroll
        for (int e = 0; e < 4; e++) o[nt][e] = 0.f;
    float mi0 = -1e30f, mi1 = -1e30f, li0 = 0.f, li1 = 0.f;

    const int qmaxw = q0 + w * 16 + 15;

    for (int c = 0; c < nch; c++) {
        if (c + 1 < nch) {
            const uint32_t sb = smem + (c & 1) * ASTAGE;   // chunk c+1 -> stage c&1
            const int k0 = (c + 1) * 64;
            #pragma unroll
            for (int i = 0; i < 8; i++) {
                const int tile = i >> 1;
                const int r    = ((i & 1) << 5) + r_lo;
                const __half* gp =
                    kvsrc[tile] + ((size_t)(b * S_LEN + k0 + r)) * D_MODEL + hbase + ch8 * 8;
                cp_async16(sb + tile * KV_TILE + r * APITCH + ch8 * 16, gp);
            }
            CP_COMMIT();
            CP_WAIT(1);
        } else {
            CP_WAIT(0);
        }
        __syncthreads();

        const int c0 = c * 64;
        const bool diag = (c0 >= q0);
        const uint32_t sb  = smem + ((c + 1) & 1) * ASTAGE;
        const uint32_t Khs = sb;
        const uint32_t Kls = sb + KV_TILE;
        const uint32_t Vhs = sb + 2 * KV_TILE;
        const uint32_t Vls = sb + 3 * KV_TILE;

        float s[8][4];
        #pragma unroll
        for (int nt = 0; nt < 8; nt++)
            #pragma unroll
            for (int e = 0; e < 4; e++) s[nt][e] = 0.f;

        #pragma unroll
        for (int ks = 0; ks < 4; ks++) {
            uint32_t kh[4][4], kl[4][4];
            #pragma unroll
            for (int p = 0; p < 4; p++) {
                if (!diag || c0 + 16 * p <= qmaxw) {
                    LDSM4(kh[p], Khs + p * 16 * APITCH + ks * 32 + boff);
                    LDSM4(kl[p], Kls + p * 16 * APITCH + ks * 32 + boff);
                }
            }
            #pragma unroll
            for (int nt = 0; nt < 8; nt++) {
                if (!diag || c0 + 8 * nt <= qmaxw) {
                    const int p = nt >> 1;
                    const int q = nt & 1;
                    MMA16816(s[nt], qh[ks], kh[p][q], kh[p][q + 2]);
                    MMA16816(s[nt], ql[ks], kh[p][q], kh[p][q + 2]);
                    MMA16816(s[nt], qh[ks], kl[p][q], kl[p][q + 2]);
                }
            }
        }

        if (diag) {
            const int qr0 = q0 + w * 16 + (lane >> 2);
            #pragma unroll
            for (int nt = 0; nt < 8; nt++)
                #pragma unroll
                for (int e = 0; e < 4; e++) {
                    const int key = c0 + nt * 8 + 2 * (lane & 3) + (e & 1);
                    const int qr  = qr0 + (e >> 1) * 8;
                    if (key > qr) s[nt][e] = -1e30f;
                }
        }

        float rmax0 = -1e30f, rmax1 = -1e30f;
        #pragma unroll
        for (int nt = 0; nt < 8; nt++) {
            rmax0 = fmaxf(rmax0, fmaxf(s[nt][0], s[nt][1]));
            rmax1 = fmaxf(rmax1, fmaxf(s[nt][2], s[nt][3]));
        }
        rmax0 = fmaxf(rmax0, __shfl_xor_sync(0xffffffffu, rmax0, 1));
        rmax0 = fmaxf(rmax0, __shfl_xor_sync(0xffffffffu, rmax0, 2));
        rmax1 = fmaxf(rmax1, __shfl_xor_sync(0xffffffffu, rmax1, 1));
        rmax1 = fmaxf(rmax1, __shfl_xor_sync(0xffffffffu, rmax1, 2));

        const float mnew0 = fmaxf(mi0, rmax0);
        const float mnew1 = fmaxf(mi1, rmax1);
        const float alpha0 = __expf(mi0 - mnew0);
        const float alpha1 = __expf(mi1 - mnew1);
        mi0 = mnew0; mi1 = mnew1;

        float rsum0 = 0.f, rsum1 = 0.f;
        #pragma unroll
        for (int nt = 0; nt < 8; nt++) {
            s[nt][0] = __expf(s[nt][0] - mnew0);
            s[nt][1] = __expf(s[nt][1] - mnew0);
            s[nt][2] = __expf(s[nt][2] - mnew1);
            s[nt][3] = __expf(s[nt][3] - mnew1);
            rsum0 += s[nt][0] + s[nt][1];
            rsum1 += s[nt][2] + s[nt][3];
        }
        rsum0 += __shfl_xor_sync(0xffffffffu, rsum0, 1);
        rsum0 += __shfl_xor_sync(0xffffffffu, rsum0, 2);
        rsum1 += __shfl_xor_sync(0xffffffffu, rsum1, 1);
        rsum1 += __shfl_xor_sync(0xffffffffu, rsum1, 2);
        li0 = li0 * alpha0 + rsum0;
        li1 = li1 * alpha1 + rsum1;

        #pragma unroll
        for (int nt = 0; nt < 8; nt++) {
            o[nt][0] *= alpha0; o[nt][1] *= alpha0;
            o[nt][2] *= alpha1; o[nt][3] *= alpha1;
        }

        #pragma unroll
        for (int kb = 0; kb < 4; kb++) {
            if (!diag || c0 + 16 * kb <= qmaxw) {
                uint32_t ph[4], pl[4];
                {
                    const float* s0 = s[2 * kb];
                    const float* s1 = s[2 * kb + 1];
                    float h00 = h_round(s0[0]), h01 = h_round(s0[1]);
                    float h02 = h_round(s0[2]), h03 = h_round(s0[3]);
                    float h10 = h_round(s1[0]), h11 = h_round(s1[1]);
                    float h12 = h_round(s1[2]), h13 = h_round(s1[3]);
                    ph[0] = h2x(s0[0], s0[1]);
                    ph[1] = h2x(s0[2], s0[3]);
                    ph[2] = h2x(s1[0], s1[1]);
                    ph[3] = h2x(s1[2], s1[3]);
                    pl[0] = h2x(s0[0] - h00, s0[1] - h01);
                    pl[1] = h2x(s0[2] - h02, s0[3] - h03);
                    pl[2] = h2x(s1[0] - h10, s1[1] - h11);
                    pl[3] = h2x(s1[2] - h12, s1[3] - h13);
                }
                #pragma unroll
                for (int dt = 0; dt < 4; dt++) {
                    uint32_t vh[4], vl[4];
                    LDSM4T(vh, Vhs + kb * 16 * APITCH + dt * 32 + voff);
                    LDSM4T(vl, Vls + kb * 16 * APITCH + dt * 32 + voff);
                    #pragma unroll
                    for (int q = 0; q < 2; q++) {
                        const int nt = dt * 2 + q;
                        MMA16816(o[nt], ph, vh[2 * q], vh[2 * q + 1]);
                        MMA16816(o[nt], pl, vh[2 * q], vh[2 * q + 1]);
                        MMA16816(o[nt], ph, vl[2 * q], vl[2 * q + 1]);
                    }
                }
            }
        }
        __syncthreads();
    }

    // ---- epilogue: normalize, fused fp16 hi/lo split store ----
    const float inv0 = 1.f / li0;
    const float inv1 = 1.f / li1;
    const int qr0 = q0 + w * 16 + (lane >> 2);
    const int cb  = hbase + 2 * (lane & 3);
    #pragma unroll
    for (int nt = 0; nt < 8; nt++) {
        const float a0 = o[nt][0] * inv0, a1 = o[nt][1] * inv0;
        const float a2 = o[nt][2] * inv1, a3 = o[nt][3] * inv1;
        const float h0 = h_round(a0), h1 = h_round(a1);
        const float h2 = h_round(a2), h3 = h_round(a3);
        const size_t i0 = ((size_t)(b * S_LEN + qr0)) * D_MODEL + cb + nt * 8;
        const size_t i1 = ((size_t)(b * S_LEN + qr0 + 8)) * D_MODEL + cb + nt * 8;
        *(uint32_t*)&AOh[i0] = h2x(a0, a1);
        *(uint32_t*)&AOl[i0] = h2x(a0 - h0, a1 - h1);
        *(uint32_t*)&AOh[i1] = h2x(a2, a3);
        *(uint32_t*)&AOl[i1] = h2x(a2 - h2, a3 - h3);
    }
}

// ---------------------------------------------------------------------------
// Launch
// ---------------------------------------------------------------------------
extern "C" void kernel_launch(void* const* d_in, const int* in_sizes, int n_in,
                              void* d_out, int out_size)
{
    const float* x  = (const float*)d_in[0];
    float* out = (float*)d_out;

    __half *pxh, *pxl, *pwh;
    __half *pqh, *pql, *pkh, *pkl, *pvh, *pvl, *paoh, *paol;
    cudaGetSymbolAddress((void**)&pxh,  g_xh);
    cudaGetSymbolAddress((void**)&pxl,  g_xl);
    cudaGetSymbolAddress((void**)&pwh,  g_wh);
    cudaGetSymbolAddress((void**)&pqh,  g_qh);
    cudaGetSymbolAddress((void**)&pql,  g_ql);
    cudaGetSymbolAddress((void**)&pkh,  g_kh);
    cudaGetSymbolAddress((void**)&pkl,  g_kl);
    cudaGetSymbolAddress((void**)&pvh,  g_vh);
    cudaGetSymbolAddress((void**)&pvl,  g_vl);
    cudaGetSymbolAddress((void**)&paoh, g_aoh);
    cudaGetSymbolAddress((void**)&paol, g_aol);

    cudaFuncSetAttribute(gemm_f16x2,
                         cudaFuncAttributeMaxDynamicSharedMemorySize, GSMEM);
    cudaFuncSetAttribute(attn_mma,
                         cudaFuncAttributeMaxDynamicSharedMemorySize, ASMEM);

    const int n4e = MROWS * KDIM / 4;
    const int n4w = KDIM * NDIM / 4;

    // 1) split x (hi/lo); convert all 4 weights to fp16 hi in one launch
    split_f16<<<(n4e + 255) / 256, 256>>>(x, pxh, pxl, n4e);
    convert_w4<<<(4 * n4w + 255) / 256, 256>>>(
        (const float*)d_in[1], (const float*)d_in[2],
        (const float*)d_in[3], (const float*)d_in[4],
        pwh, n4w);

    // 2) Q/K/V projections with fused hi/lo split epilogue (Q scaled 1/8)
    dim3 ggrid(NDIM / 256, MROWS / 128);   // (4, 32)
    gemm_f16x2<<<ggrid, 256, GSMEM>>>(pxh, pxl,
        pwh + 0 * (size_t)KDIM * NDIM,
        (float*)nullptr, pqh, pql, 0.125f);
    gemm_f16x2<<<ggrid, 256, GSMEM>>>(pxh, pxl,
        pwh + 1 * (size_t)KDIM * NDIM,
        (float*)nullptr, pkh, pkl, 1.f);
    gemm_f16x2<<<ggrid, 256, GSMEM>>>(pxh, pxl,
        pwh + 2 * (size_t)KDIM * NDIM,
        (float*)nullptr, pvh, pvl, 1.f);

    // 3) tensor-core causal attention (fp16x3, fused split epilogue)
    dim3 agrid(NQT, NHEAD, B_SZ);          // (16, 16, 2)
    attn_mma<<<agrid, 256, ASMEM>>>(pqh, pql, pkh, pkl, pvh, pvl, paoh, paol);

    // 4) output projection -> fp32 out
    gemm_f16x2<<<ggrid, 256, GSMEM>>>(paoh, paol,
        pwh + 3 * (size_t)KDIM * NDIM,
        out, (__half*)nullptr, (__half*)nullptr, 1.f);
}

// round 16
// speedup vs baseline: 1.5191x; 1.1811x over previous
#include <cuda_runtime.h>
#include <cuda_fp16.h>
#include <cstdint>
#include <math.h>

// ---------------------------------------------------------------------------
// Problem constants
// ---------------------------------------------------------------------------
#define B_SZ    2
#define S_LEN   2048
#define D_MODEL 1024
#define NHEAD   16
#define DKH     64
#define MROWS   4096
#define KDIM    1024
#define NDIM    1024
#define NQT     (S_LEN / 128)     // 16 q-tiles of 128 rows

// ---------------------------------------------------------------------------
// Scratch (device globals)
// ---------------------------------------------------------------------------
__device__ __align__(16) __half g_xh [MROWS * KDIM];
__device__ __align__(16) __half g_xl [MROWS * KDIM];
__device__ __align__(16) __half g_wh [4 * KDIM * NDIM];     // weights hi only
__device__ __align__(16) __half g_qh [MROWS * D_MODEL];
__device__ __align__(16) __half g_ql [MROWS * D_MODEL];
__device__ __align__(16) __half g_kh [MROWS * D_MODEL];
__device__ __align__(16) __half g_vh [MROWS * D_MODEL];
__device__ __align__(16) __half g_aoh[MROWS * D_MODEL];
__device__ __align__(16) __half g_aol[MROWS * D_MODEL];

// ---------------------------------------------------------------------------
// PTX helpers (sm_80-era, valid at compute_100)
// ---------------------------------------------------------------------------
__device__ __forceinline__ uint32_t smem_u32(const void* p) {
    uint32_t a;
    asm("{ .reg .u64 t; cvta.to.shared.u64 t, %1; cvt.u32.u64 %0, t; }"
        : "=r"(a) : "l"(p));
    return a;
}

__device__ __forceinline__ void cp_async16(uint32_t dst, const void* src) {
    asm volatile("cp.async.cg.shared.global [%0], [%1], 16;"
                 :: "r"(dst), "l"(src) : "memory");
}
#define CP_COMMIT() asm volatile("cp.async.commit_group;" ::: "memory")
#define CP_WAIT(n)  asm volatile("cp.async.wait_group %0;" :: "n"(n) : "memory")

#define LDSM4(r, addr) \
    asm volatile("ldmatrix.sync.aligned.m8n8.x4.shared.b16 {%0,%1,%2,%3}, [%4];" \
                 : "=r"((r)[0]), "=r"((r)[1]), "=r"((r)[2]), "=r"((r)[3]) : "r"(addr))

#define LDSM4T(r, addr) \
    asm volatile("ldmatrix.sync.aligned.m8n8.x4.trans.shared.b16 {%0,%1,%2,%3}, [%4];" \
                 : "=r"((r)[0]), "=r"((r)[1]), "=r"((r)[2]), "=r"((r)[3]) : "r"(addr))

#define MMA16816(d, a, b0v, b1v) \
    asm volatile("mma.sync.aligned.m16n8k16.row.col.f32.f16.f16.f32 " \
                 "{%0,%1,%2,%3}, {%4,%5,%6,%7}, {%8,%9}, {%0,%1,%2,%3};" \
                 : "+f"((d)[0]), "+f"((d)[1]), "+f"((d)[2]), "+f"((d)[3]) \
                 : "r"((a)[0]), "r"((a)[1]), "r"((a)[2]), "r"((a)[3]), \
                   "r"(b0v), "r"(b1v))

// pack two fp32 -> half2 (first arg in low 16 bits)
__device__ __forceinline__ uint32_t h2x(float lo, float hi) {
    __half2 h = __floats2half2_rn(lo, hi);
    return *(uint32_t*)&h;
}
__device__ __forceinline__ float h_round(float x) {
    return __half2float(__float2half_rn(x));
}

// ---------------------------------------------------------------------------
// fp32 -> fp16 hi/lo split for x; fp32 -> fp16 (hi only) for the 4 weights
// ---------------------------------------------------------------------------
__global__ __launch_bounds__(256)
void split_f16(const float* __restrict__ in, __half* __restrict__ hi,
               __half* __restrict__ lo, int n4)
{
    int i = blockIdx.x * blockDim.x + threadIdx.x;
    if (i >= n4) return;
    float4 v = ((const float4*)in)[i];
    float f[4] = {v.x, v.y, v.z, v.w};
    unsigned short hs[4], ls[4];
    #pragma unroll
    for (int j = 0; j < 4; j++) {
        __half h = __float2half_rn(f[j]);
        float r = f[j] - __half2float(h);
        __half l = __float2half_rn(r);
        hs[j] = __half_as_ushort(h);
        ls[j] = __half_as_ushort(l);
    }
    ((ushort4*)hi)[i] = make_ushort4(hs[0], hs[1], hs[2], hs[3]);
    ((ushort4*)lo)[i] = make_ushort4(ls[0], ls[1], ls[2], ls[3]);
}

__global__ __launch_bounds__(256)
void convert_w4(const float* __restrict__ w0, const float* __restrict__ w1,
                const float* __restrict__ w2, const float* __restrict__ w3,
                __half* __restrict__ hi, int n4w)
{
    int i = blockIdx.x * blockDim.x + threadIdx.x;
    if (i >= 4 * n4w) return;
    const int m = i / n4w;
    const int j = i - m * n4w;
    const float* src = (m == 0) ? w0 : (m == 1) ? w1 : (m == 2) ? w2 : w3;
    float4 v = ((const float4*)src)[j];
    ushort4 o;
    o.x = __half_as_ushort(__float2half_rn(v.x));
    o.y = __half_as_ushort(__float2half_rn(v.y));
    o.z = __half_as_ushort(__float2half_rn(v.z));
    o.w = __half_as_ushort(__float2half_rn(v.w));
    ((ushort4*)hi)[i] = o;
}

// ---------------------------------------------------------------------------
// fp16x2-split GEMM via mma.sync:  C = (Ah+Al) Bh^T (NT), 128x256x64 tile.
// 256 threads, 8 warps (2m x 4n), warp tile 64x64. BK=64, 2-stage cp.async.
// Epilogue: fp32 (Cf) and/or fp16 hi (Ch) and/or fp16 lo (Cl) — independent.
// ---------------------------------------------------------------------------
#define GP      144                   // smem row pitch (128B data + 16B pad)
#define ATB     (128 * GP)            // 18432
#define BTB     (256 * GP)            // 36864
#define STG     (2 * ATB + BTB)       // 73728
#define GSMEM   (2 * STG)             // 147456
#define KT      (KDIM / 64)           // 16

__global__ __launch_bounds__(256, 1)
void gemm_f16x2(const __half* __restrict__ Agh,
                const __half* __restrict__ Agl,
                const __half* __restrict__ Bgh,
                float* __restrict__ Cf,
                __half* __restrict__ Ch,
                __half* __restrict__ Cl,
                float scale)
{
    extern __shared__ __align__(128) char smem_raw[];
    const uint32_t smem = smem_u32(smem_raw);

    const int tid    = threadIdx.x;
    const int lane   = tid & 31;
    const int wid    = tid >> 5;
    const int warp_m = wid & 1;
    const int warp_n = wid >> 1;
    const int row0   = blockIdx.y * 128;
    const int col0   = blockIdx.x * 256;

    const uint32_t aoff = (uint32_t)((lane & 15) * GP + ((lane >> 4) << 4));
    const uint32_t boff = (uint32_t)((((lane >> 3) & 1) * 8 + (lane & 7)) * GP +
                                     ((lane >> 4) << 4));

    float acc[4][8][4];
    #pragma unroll
    for (int mt = 0; mt < 4; mt++)
        #pragma unroll
        for (int nt = 0; nt < 8; nt++)
            #pragma unroll
            for (int q = 0; q < 4; q++) acc[mt][nt][q] = 0.f;

    const int rt  = tid >> 3;           // 0..31 row within 32-row group
    const int ch8 = tid & 7;            // 16B chunk within 128B row payload

    #define LOAD_STAGE(sb, k0)                                                  \
    do {                                                                        \
        const size_t kofs = (size_t)(k0) + ch8 * 8;                             \
        _Pragma("unroll")                                                       \
        for (int rr = 0; rr < 4; rr++) {                                        \
            const int r = rr * 32 + rt;                                         \
            cp_async16((sb) + r * GP + ch8 * 16,                                \
                       Agh + (size_t)(row0 + r) * KDIM + kofs);                 \
            cp_async16((sb) + ATB + r * GP + ch8 * 16,                          \
                       Agl + (size_t)(row0 + r) * KDIM + kofs);                 \
        }                                                                       \
        _Pragma("unroll")                                                       \
        for (int rr = 0; rr < 8; rr++) {                                        \
            const int r = rr * 32 + rt;                                         \
            cp_async16((sb) + 2 * ATB + r * GP + ch8 * 16,                      \
                       Bgh + (size_t)(col0 + r) * KDIM + kofs);                 \
        }                                                                       \
    } while (0)

    LOAD_STAGE(smem, 0);
    CP_COMMIT();

    for (int t = 0; t < KT; t++) {
        const int cur = t & 1;
        if (t + 1 < KT) {
            const uint32_t sb = smem + ((t + 1) & 1) * STG;
            LOAD_STAGE(sb, (t + 1) * 64);
            CP_COMMIT();
            CP_WAIT(1);
        } else {
            CP_WAIT(0);
        }
        __syncthreads();

        const uint32_t sb  = smem + cur * STG;
        const uint32_t Ahs = sb;
        const uint32_t Bhs = sb + 2 * ATB;

        #pragma unroll
        for (int kk = 0; kk < 4; kk++) {
            const uint32_t kkb = kk * 32;
            uint32_t ah[4][4];
            uint32_t al[4][4];
            uint32_t bh[4][4];
            #pragma unroll
            for (int mt = 0; mt < 4; mt++) {
                const uint32_t ad = Ahs + (warp_m * 64 + mt * 16) * GP + kkb + aoff;
                LDSM4(ah[mt], ad);
                LDSM4(al[mt], ad + ATB);
            }
            #pragma unroll
            for (int p = 0; p < 4; p++) {
                const uint32_t bd = Bhs + (warp_n * 64 + p * 16) * GP + kkb + boff;
                LDSM4(bh[p], bd);
            }
            #pragma unroll
            for (int mt = 0; mt < 4; mt++)
                #pragma unroll
                for (int nt = 0; nt < 8; nt++) {
                    float* d = acc[mt][nt];
                    const int p = nt >> 1;
                    const int q = nt & 1;
                    MMA16816(d, ah[mt], bh[p][q], bh[p][q + 2]);
                    MMA16816(d, al[mt], bh[p][q], bh[p][q + 2]);
                }
        }
        __syncthreads();
    }
    #undef LOAD_STAGE

    // ---- epilogue ----
    const int rbase = row0 + warp_m * 64 + (lane >> 2);
    const int cbase = col0 + warp_n * 64 + (lane & 3) * 2;
    #pragma unroll
    for (int mt = 0; mt < 4; mt++) {
        #pragma unroll
        for (int nt = 0; nt < 8; nt++) {
            const int r = rbase + mt * 16;
            const int c = cbase + nt * 8;
            const float v0 = acc[mt][nt][0] * scale;
            const float v1 = acc[mt][nt][1] * scale;
            const float v2 = acc[mt][nt][2] * scale;
            const float v3 = acc[mt][nt][3] * scale;
            if (Cf) {
                *(float2*)&Cf[(size_t)r * NDIM + c]       = make_float2(v0, v1);
                *(float2*)&Cf[(size_t)(r + 8) * NDIM + c] = make_float2(v2, v3);
            }
            if (Ch) {
                *(uint32_t*)&Ch[(size_t)r * NDIM + c]       = h2x(v0, v1);
                *(uint32_t*)&Ch[(size_t)(r + 8) * NDIM + c] = h2x(v2, v3);
            }
            if (Cl) {
                const float h0 = h_round(v0), h1 = h_round(v1);
                const float h2 = h_round(v2), h3 = h_round(v3);
                *(uint32_t*)&Cl[(size_t)r * NDIM + c]       = h2x(v0 - h0, v1 - h1);
                *(uint32_t*)&Cl[(size_t)(r + 8) * NDIM + c] = h2x(v2 - h2, v3 - h3);
            }
        }
    }
}

// ---------------------------------------------------------------------------
// Tensor-core causal flash attention, fp16x2 split:
//   S = (Qh+Ql) Kh^T,  O = (Ph+Pl) Vh    (K/V lo terms dropped, ~2^-12 err)
// 256 threads, 8 warps, 128-row q-tile. K/V chunk = Kh+Vh only (2 tiles),
// Q has its own smem region so Q-load overlaps the chunk-0 prefetch.
// ---------------------------------------------------------------------------
#define APITCH  144
#define KV_TILE (64 * APITCH)       // 9216
#define KVSTG   (2 * KV_TILE)       // 18432 (Kh, Vh)
#define QOFF    (2 * KVSTG)         // 36864
#define QTB     (128 * APITCH)      // 18432
#define ASMEM   (QOFF + 2 * QTB)    // 73728

__global__ __launch_bounds__(256, 1)
void attn_mma(const __half* __restrict__ Qh_, const __half* __restrict__ Ql_,
              const __half* __restrict__ Kh_, const __half* __restrict__ Vh_,
              __half* __restrict__ AOh, __half* __restrict__ AOl)
{
    extern __shared__ __align__(128) char smx[];
    const uint32_t smem = smem_u32(smx);
    const int tid  = threadIdx.x;
    const int lane = tid & 31;
    const int w    = tid >> 5;
    const int qt   = (NQT - 1) - blockIdx.x;
    const int h    = blockIdx.y;
    const int b    = blockIdx.z;
    const int q0   = qt * 128;
    const int hbase = h * 64;

    const uint32_t aoff = (uint32_t)((lane & 15) * APITCH + ((lane >> 4) << 4));
    const uint32_t boff = (uint32_t)((((lane >> 3) & 1) * 8 + (lane & 7)) * APITCH +
                                     ((lane >> 4) << 4));
    const uint32_t voff = aoff;

    const int nch  = 2 * (qt + 1);
    const int r_lo = tid >> 3;           // 0..31
    const int ch8  = tid & 7;

    // ---- prologue: Q (own region) and chunk 0 (stage 1) in flight together ----
    {
        const int r  = tid >> 1;         // 0..127
        const int c4 = (tid & 1) * 4;
        const size_t gq = ((size_t)(b * S_LEN + q0 + r)) * D_MODEL + hbase;
        const uint32_t d0 = smem + QOFF + r * APITCH;
        #pragma unroll
        for (int j = 0; j < 4; j++) {
            cp_async16(d0 + (c4 + j) * 16, Qh_ + gq + (c4 + j) * 8);
            cp_async16(d0 + QTB + (c4 + j) * 16, Ql_ + gq + (c4 + j) * 8);
        }
        CP_COMMIT();
    }
    {
        const uint32_t sb = smem + KVSTG;   // chunk 0 -> stage 1
        #pragma unroll
        for (int i = 0; i < 4; i++) {
            const int tile = i >> 1;         // 0=K, 1=V
            const int r    = ((i & 1) << 5) + r_lo;
            const __half* gp = (tile ? Vh_ : Kh_) +
                ((size_t)(b * S_LEN + r)) * D_MODEL + hbase + ch8 * 8;
            cp_async16(sb + tile * KV_TILE + r * APITCH + ch8 * 16, gp);
        }
        CP_COMMIT();
    }
    CP_WAIT(1);          // Q group done
    __syncthreads();

    uint32_t qh[4][4], ql[4][4];
    {
        const uint32_t qtb = smem + QOFF + (w * 16) * APITCH;
        #pragma unroll
        for (int ks = 0; ks < 4; ks++) {
            LDSM4(qh[ks], qtb + ks * 32 + aoff);
            LDSM4(ql[ks], qtb + QTB + ks * 32 + aoff);
        }
    }

    float o[8][4];
    #pragma unroll
    for (int nt = 0; nt < 8; nt++)
        #pragma unroll
        for (int e = 0; e < 4; e++) o[nt][e] = 0.f;
    float mi0 = -1e30f, mi1 = -1e30f, li0 = 0.f, li1 = 0.f;

    const int qmaxw = q0 + w * 16 + 15;

    for (int c = 0; c < nch; c++) {
        if (c + 1 < nch) {
            const uint32_t sb = smem + (c & 1) * KVSTG;   // chunk c+1 -> stage c&1
            const int k0 = (c + 1) * 64;
            #pragma unroll
            for (int i = 0; i < 4; i++) {
                const int tile = i >> 1;
                const int r    = ((i & 1) << 5) + r_lo;
                const __half* gp = (tile ? Vh_ : Kh_) +
                    ((size_t)(b * S_LEN + k0 + r)) * D_MODEL + hbase + ch8 * 8;
                cp_async16(sb + tile * KV_TILE + r * APITCH + ch8 * 16, gp);
            }
            CP_COMMIT();
            CP_WAIT(1);
        } else {
            CP_WAIT(0);
        }
        __syncthreads();

        const int c0 = c * 64;
        const bool diag = (c0 >= q0);
        const uint32_t sb  = smem + ((c + 1) & 1) * KVSTG;
        const uint32_t Khs = sb;
        const uint32_t Vhs = sb + KV_TILE;

        float s[8][4];
        #pragma unroll
        for (int nt = 0; nt < 8; nt++)
            #pragma unroll
            for (int e = 0; e < 4; e++) s[nt][e] = 0.f;

        #pragma unroll
        for (int ks = 0; ks < 4; ks++) {
            uint32_t kh[4][4];
            #pragma unroll
            for (int p = 0; p < 4; p++) {
                if (!diag || c0 + 16 * p <= qmaxw) {
                    LDSM4(kh[p], Khs + p * 16 * APITCH + ks * 32 + boff);
                }
            }
            #pragma unroll
            for (int nt = 0; nt < 8; nt++) {
                if (!diag || c0 + 8 * nt <= qmaxw) {
                    const int p = nt >> 1;
                    const int q = nt & 1;
                    MMA16816(s[nt], qh[ks], kh[p][q], kh[p][q + 2]);
                    MMA16816(s[nt], ql[ks], kh[p][q], kh[p][q + 2]);
                }
            }
        }

        if (diag) {
            const int qr0 = q0 + w * 16 + (lane >> 2);
            #pragma unroll
            for (int nt = 0; nt < 8; nt++)
                #pragma unroll
                for (int e = 0; e < 4; e++) {
                    const int key = c0 + nt * 8 + 2 * (lane & 3) + (e & 1);
                    const int qr  = qr0 + (e >> 1) * 8;
                    if (key > qr) s[nt][e] = -1e30f;
                }
        }

        float rmax0 = -1e30f, rmax1 = -1e30f;
        #pragma unroll
        for (int nt = 0; nt < 8; nt++) {
            rmax0 = fmaxf(rmax0, fmaxf(s[nt][0], s[nt][1]));
            rmax1 = fmaxf(rmax1, fmaxf(s[nt][2], s[nt][3]));
        }
        rmax0 = fmaxf(rmax0, __shfl_xor_sync(0xffffffffu, rmax0, 1));
        rmax0 = fmaxf(rmax0, __shfl_xor_sync(0xffffffffu, rmax0, 2));
        rmax1 = fmaxf(rmax1, __shfl_xor_sync(0xffffffffu, rmax1, 1));
        rmax1 = fmaxf(rmax1, __shfl_xor_sync(0xffffffffu, rmax1, 2));

        const float mnew0 = fmaxf(mi0, rmax0);
        const float mnew1 = fmaxf(mi1, rmax1);
        const float alpha0 = __expf(mi0 - mnew0);
        const float alpha1 = __expf(mi1 - mnew1);
        mi0 = mnew0; mi1 = mnew1;

        float rsum0 = 0.f, rsum1 = 0.f;
        #pragma unroll
        for (int nt = 0; nt < 8; nt++) {
            s[nt][0] = __expf(s[nt][0] - mnew0);
            s[nt][1] = __expf(s[nt][1] - mnew0);
            s[nt][2] = __expf(s[nt][2] - mnew1);
            s[nt][3] = __expf(s[nt][3] - mnew1);
            rsum0 += s[nt][0] + s[nt][1];
            rsum1 += s[nt][2] + s[nt][3];
        }
        rsum0 += __shfl_xor_sync(0xffffffffu, rsum0, 1);
        rsum0 += __shfl_xor_sync(0xffffffffu, rsum0, 2);
        rsum1 += __shfl_xor_sync(0xffffffffu, rsum1, 1);
        rsum1 += __shfl_xor_sync(0xffffffffu, rsum1, 2);
        li0 = li0 * alpha0 + rsum0;
        li1 = li1 * alpha1 + rsum1;

        #pragma unroll
        for (int nt = 0; nt < 8; nt++) {
            o[nt][0] *= alpha0; o[nt][1] *= alpha0;
            o[nt][2] *= alpha1; o[nt][3] *= alpha1;
        }

        #pragma unroll
        for (int kb = 0; kb < 4; kb++) {
            if (!diag || c0 + 16 * kb <= qmaxw) {
                uint32_t ph[4], pl[4];
                {
                    const float* s0 = s[2 * kb];
                    const float* s1 = s[2 * kb + 1];
                    float h00 = h_round(s0[0]), h01 = h_round(s0[1]);
                    float h02 = h_round(s0[2]), h03 = h_round(s0[3]);
                    float h10 = h_round(s1[0]), h11 = h_round(s1[1]);
                    float h12 = h_round(s1[2]), h13 = h_round(s1[3]);
                    ph[0] = h2x(s0[0], s0[1]);
                    ph[1] = h2x(s0[2], s0[3]);
                    ph[2] = h2x(s1[0], s1[1]);
                    ph[3] = h2x(s1[2], s1[3]);
                    pl[0] = h2x(s0[0] - h00, s0[1] - h01);
                    pl[1] = h2x(s0[2] - h02, s0[3] - h03);
                    pl[2] = h2x(s1[0] - h10, s1[1] - h11);
                    pl[3] = h2x(s1[2] - h12, s1[3] - h13);
                }
                #pragma unroll
                for (int dt = 0; dt < 4; dt++) {
                    uint32_t vh[4];
                    LDSM4T(vh, Vhs + kb * 16 * APITCH + dt * 32 + voff);
                    #pragma unroll
                    for (int q = 0; q < 2; q++) {
                        const int nt = dt * 2 + q;
                        MMA16816(o[nt], ph, vh[2 * q], vh[2 * q + 1]);
                        MMA16816(o[nt], pl, vh[2 * q], vh[2 * q + 1]);
                    }
                }
            }
        }
        __syncthreads();
    }

    // ---- epilogue: normalize, fused fp16 hi/lo split store ----
    const float inv0 = 1.f / li0;
    const float inv1 = 1.f / li1;
    const int qr0 = q0 + w * 16 + (lane >> 2);
    const int cb  = hbase + 2 * (lane & 3);
    #pragma unroll
    for (int nt = 0; nt < 8; nt++) {
        const float a0 = o[nt][0] * inv0, a1 = o[nt][1] * inv0;
        const float a2 = o[nt][2] * inv1, a3 = o[nt][3] * inv1;
        const float h0 = h_round(a0), h1 = h_round(a1);
        const float h2 = h_round(a2), h3 = h_round(a3);
        const size_t i0 = ((size_t)(b * S_LEN + qr0)) * D_MODEL + cb + nt * 8;
        const size_t i1 = ((size_t)(b * S_LEN + qr0 + 8)) * D_MODEL + cb + nt * 8;
        *(uint32_t*)&AOh[i0] = h2x(a0, a1);
        *(uint32_t*)&AOl[i0] = h2x(a0 - h0, a1 - h1);
        *(uint32_t*)&AOh[i1] = h2x(a2, a3);
        *(uint32_t*)&AOl[i1] = h2x(a2 - h2, a3 - h3);
    }
}

// ---------------------------------------------------------------------------
// Launch
// ---------------------------------------------------------------------------
extern "C" void kernel_launch(void* const* d_in, const int* in_sizes, int n_in,
                              void* d_out, int out_size)
{
    const float* x  = (const float*)d_in[0];
    float* out = (float*)d_out;

    __half *pxh, *pxl, *pwh;
    __half *pqh, *pql, *pkh, *pvh, *paoh, *paol;
    cudaGetSymbolAddress((void**)&pxh,  g_xh);
    cudaGetSymbolAddress((void**)&pxl,  g_xl);
    cudaGetSymbolAddress((void**)&pwh,  g_wh);
    cudaGetSymbolAddress((void**)&pqh,  g_qh);
    cudaGetSymbolAddress((void**)&pql,  g_ql);
    cudaGetSymbolAddress((void**)&pkh,  g_kh);
    cudaGetSymbolAddress((void**)&pvh,  g_vh);
    cudaGetSymbolAddress((void**)&paoh, g_aoh);
    cudaGetSymbolAddress((void**)&paol, g_aol);

    cudaFuncSetAttribute(gemm_f16x2,
                         cudaFuncAttributeMaxDynamicSharedMemorySize, GSMEM);
    cudaFuncSetAttribute(attn_mma,
                         cudaFuncAttributeMaxDynamicSharedMemorySize, ASMEM);

    const int n4e = MROWS * KDIM / 4;
    const int n4w = KDIM * NDIM / 4;

    // 1) split x (hi/lo); convert all 4 weights to fp16 hi in one launch
    split_f16<<<(n4e + 255) / 256, 256>>>(x, pxh, pxl, n4e);
    convert_w4<<<(4 * n4w + 255) / 256, 256>>>(
        (const float*)d_in[1], (const float*)d_in[2],
        (const float*)d_in[3], (const float*)d_in[4],
        pwh, n4w);

    // 2) Q/K/V projections (Q: hi+lo, scaled 1/8; K/V: hi only)
    dim3 ggrid(NDIM / 256, MROWS / 128);   // (4, 32)
    gemm_f16x2<<<ggrid, 256, GSMEM>>>(pxh, pxl,
        pwh + 0 * (size_t)KDIM * NDIM,
        (float*)nullptr, pqh, pql, 0.125f);
    gemm_f16x2<<<ggrid, 256, GSMEM>>>(pxh, pxl,
        pwh + 1 * (size_t)KDIM * NDIM,
        (float*)nullptr, pkh, (__half*)nullptr, 1.f);
    gemm_f16x2<<<ggrid, 256, GSMEM>>>(pxh, pxl,
        pwh + 2 * (size_t)KDIM * NDIM,
        (float*)nullptr, pvh, (__half*)nullptr, 1.f);

    // 3) tensor-core causal attention (fp16x2, fused split epilogue)
    dim3 agrid(NQT, NHEAD, B_SZ);          // (16, 16, 2)
    attn_mma<<<agrid, 256, ASMEM>>>(pqh, pql, pkh, pvh, paoh, paol);

    // 4) output projection -> fp32 out
    gemm_f16x2<<<ggrid, 256, GSMEM>>>(paoh, paol,
        pwh + 3 * (size_t)KDIM * NDIM,
        out, (__half*)nullptr, (__half*)nullptr, 1.f);
}